// round 4
// baseline (speedup 1.0000x reference)
#include <cuda_runtime.h>
#include <math.h>

// ----------------------------------------------------------------------------
// Radial NUFFT pipeline (exact NDFT), N=192 image, M=36864 samples.
// f32x2 (packed FFMA2) version: both GEMM kernels use fma.rn.f32x2 to reach
// the full 128-FMA/cyc/SM fp32 datapath on sm_103a.
// ----------------------------------------------------------------------------

#define NPIX   192
#define MPTS   (NPIX * NPIX)        // 36864
#define NN     (NPIX * NPIX)
#define NCHUNK 64                    // split-K chunks for adjoint
#define KCHUNK (MPTS / NCHUNK)       // 576
#define TWO_PI_F 6.28318530717958647693f

typedef unsigned long long u64;
#define SGN2 0x8000000080000000ULL   // sign-bit mask for both halves of f32x2

// -------------------- f32x2 helpers ------------------------------------------
__device__ __forceinline__ u64 pk2(float lo, float hi) {
    u64 r; asm("mov.b64 %0, {%1,%2};" : "=l"(r) : "f"(lo), "f"(hi)); return r;
}
__device__ __forceinline__ u64 bc2(float v) { return pk2(v, v); }
__device__ __forceinline__ void fma2(u64& d, u64 a, u64 b) {
    asm("fma.rn.f32x2 %0, %1, %2, %0;" : "+l"(d) : "l"(a), "l"(b));
}
__device__ __forceinline__ float lo2(u64 v) {
    float a, b; asm("mov.b64 {%0,%1}, %2;" : "=f"(a), "=f"(b) : "l"(v)); return a;
}
__device__ __forceinline__ float hi2(u64 v) {
    float a, b; asm("mov.b64 {%0,%1}, %2;" : "=f"(a), "=f"(b) : "l"(v)); return b;
}
__device__ __forceinline__ float sum2(u64 v) { return lo2(v) + hi2(v); }

// -------------------- scratch (device globals; no allocations) --------------
static __device__ __align__(16) float g_Ar[MPTS * NPIX];
static __device__ __align__(16) float g_Ai[MPTS * NPIX];
static __device__ __align__(16) float g_Br[MPTS * NPIX];
static __device__ __align__(16) float g_Bi[MPTS * NPIX];

static __device__ __align__(16) float g_imgT_re[NN],  g_imgT_im[NN];   // [y][x]
static __device__ __align__(16) float g_imgwT_re[NN], g_imgwT_im[NN];  // [y][x]

static __device__ float g_w[MPTS];
static __device__ float g_dre[MPTS], g_dim[MPTS];
static __device__ float g_sre[MPTS], g_sim[MPTS];

static __device__ __align__(16) float g_part[NCHUNK * 2 * NN];

// -------------------- build A, B ---------------------------------------------
__global__ void k_build(const float* __restrict__ traj) {
    int idx = blockIdx.x * blockDim.x + threadIdx.x;
    if (idx >= MPTS * NPIX) return;
    int m = idx / NPIX;
    int x = idx - m * NPIX;
    float p  = (float)x - 96.0f;
    float kx = traj[2 * m];
    float ky = traj[2 * m + 1];

    float s, c, ph, r;
    ph = kx * p; r = ph - rintf(ph);
    __sincosf(TWO_PI_F * r, &s, &c);
    g_Ar[idx] = c;  g_Ai[idx] = -s;

    ph = ky * p; r = ph - rintf(ph);
    __sincosf(TWO_PI_F * r, &s, &c);
    g_Br[idx] = c;  g_Bi[idx] = -s;
}

// -------------------- image transpose ----------------------------------------
__global__ void k_transpose_in(const float* __restrict__ xin) {
    int idx = blockIdx.x * blockDim.x + threadIdx.x;
    if (idx >= NN) return;
    int x = idx / NPIX, y = idx - x * NPIX;
    g_imgT_re[y * NPIX + x] = xin[idx];
    g_imgT_im[y * NPIX + x] = xin[NN + idx];
}

// -------------------- tiny per-sample kernels --------------------------------
__global__ void k_winit() {
    int i = blockIdx.x * blockDim.x + threadIdx.x;
    if (i < MPTS) g_w[i] = 1.0f;
}
__global__ void k_dfromw() {
    int i = blockIdx.x * blockDim.x + threadIdx.x;
    if (i < MPTS) { g_dre[i] = g_w[i]; g_dim[i] = 0.0f; }
}
__global__ void k_wupdate() {
    int i = blockIdx.x * blockDim.x + threadIdx.x;
    if (i < MPTS) {
        float qr = g_sre[i], qi = g_sim[i];
        float mag = sqrtf(qr * qr + qi * qi);
        g_w[i] = g_w[i] / fmaxf(mag, 1e-20f);
    }
}
__global__ void k_dscale() {
    int i = blockIdx.x * blockDim.x + threadIdx.x;
    if (i < MPTS) {
        float w = g_w[i];
        g_dre[i] = w * g_sre[i];
        g_dim[i] = w * g_sim[i];
    }
}

// -------------------- forward op ----------------------------------------------
// s[m] = sum_x A[m,x] * (sum_y B[m,y] img[x,y]).
// Thread owns x = 2*lane + 64*j (3 f32x2 pairs), warp owns 2 m's.
__global__ void __launch_bounds__(256) k_op(int src) {
    __shared__ float sIr[16][192];
    __shared__ float sIi[16][192];
    __shared__ float sBr[16][16];
    __shared__ float sBi[16][16];

    const float* __restrict__ gTr = src ? g_imgwT_re : g_imgT_re;
    const float* __restrict__ gTi = src ? g_imgwT_im : g_imgT_im;

    int m0   = blockIdx.x * 16;
    int t    = threadIdx.x;
    int lane = t & 31;
    int wrp  = t >> 5;

    u64 accr[2][3], acci[2][3];
#pragma unroll
    for (int a = 0; a < 2; ++a)
#pragma unroll
        for (int j = 0; j < 3; ++j) { accr[a][j] = 0ULL; acci[a][j] = 0ULL; }

    for (int y0 = 0; y0 < NPIX; y0 += 16) {
        for (int i = t; i < 16 * 192; i += 256) {
            int yl = i / 192, x = i - yl * 192;
            sIr[yl][x] = gTr[(y0 + yl) * NPIX + x];
            sIi[yl][x] = gTi[(y0 + yl) * NPIX + x];
        }
        {
            int ml = t >> 4, yl = t & 15;
            sBr[ml][yl] = g_Br[(m0 + ml) * NPIX + y0 + yl];
            sBi[ml][yl] = g_Bi[(m0 + ml) * NPIX + y0 + yl];
        }
        __syncthreads();

#pragma unroll
        for (int k = 0; k < 16; ++k) {
            u64 pbr0  = bc2(sBr[2 * wrp][k]);
            u64 pbi0  = bc2(sBi[2 * wrp][k]);
            u64 pnbi0 = pbi0 ^ SGN2;
            u64 pbr1  = bc2(sBr[2 * wrp + 1][k]);
            u64 pbi1  = bc2(sBi[2 * wrp + 1][k]);
            u64 pnbi1 = pbi1 ^ SGN2;
#pragma unroll
            for (int j = 0; j < 3; ++j) {
                int x = 2 * lane + 64 * j;
                u64 gr = *reinterpret_cast<const u64*>(&sIr[k][x]);
                u64 gi = *reinterpret_cast<const u64*>(&sIi[k][x]);
                fma2(accr[0][j], pbr0,  gr);
                fma2(accr[0][j], pnbi0, gi);
                fma2(acci[0][j], pbr0,  gi);
                fma2(acci[0][j], pbi0,  gr);
                fma2(accr[1][j], pbr1,  gr);
                fma2(accr[1][j], pnbi1, gi);
                fma2(acci[1][j], pbr1,  gi);
                fma2(acci[1][j], pbi1,  gr);
            }
        }
        __syncthreads();
    }

    // epilogue: k[m] = sum_x A[m,x] * t[m,x]  (no conj on forward op)
#pragma unroll
    for (int mi = 0; mi < 2; ++mi) {
        int m = m0 + 2 * wrp + mi;
        u64 prv = 0ULL, piv = 0ULL;
#pragma unroll
        for (int j = 0; j < 3; ++j) {
            int x = 2 * lane + 64 * j;
            u64 ar  = *reinterpret_cast<const u64*>(&g_Ar[m * NPIX + x]);
            u64 ai  = *reinterpret_cast<const u64*>(&g_Ai[m * NPIX + x]);
            u64 nai = ai ^ SGN2;
            fma2(prv, ar,  accr[mi][j]);
            fma2(prv, nai, acci[mi][j]);
            fma2(piv, ar,  acci[mi][j]);
            fma2(piv, ai,  accr[mi][j]);
        }
        float pr = sum2(prv), pi = sum2(piv);
#pragma unroll
        for (int o = 16; o > 0; o >>= 1) {
            pr += __shfl_xor_sync(0xffffffffu, pr, o);
            pi += __shfl_xor_sync(0xffffffffu, pi, o);
        }
        if (lane == 0) { g_sre[m] = pr; g_sim[m] = pi; }
    }
}

// -------------------- adjoint --------------------------------------------------
// out[x,y] = sum_m conj(A[m,x]) d[m] conj(B[m,y]).
// Out tile 48(x) x 64(y); thread tile 3(x) x 4(y), y vectorized as 2 f32x2.
// grid (4, 3, NCHUNK), block 256 (tx = y index, ty = x index).
__global__ void __launch_bounds__(256) k_adj() {
    __shared__ float sEr[32][48];
    __shared__ float sEi[32][48];
    __shared__ float sCr[32][64];
    __shared__ float sCi[32][64];

    int x0    = blockIdx.x * 48;
    int y0    = blockIdx.y * 64;
    int mbase = blockIdx.z * KCHUNK;
    int t  = threadIdx.x;
    int tx = t & 15;        // -> y
    int ty = t >> 4;        // -> x

    u64 accr[3][2], acci[3][2];
#pragma unroll
    for (int a = 0; a < 3; ++a)
#pragma unroll
        for (int p = 0; p < 2; ++p) { accr[a][p] = 0ULL; acci[a][p] = 0ULL; }

    for (int kk = 0; kk < KCHUNK; kk += 32) {
        // stage E = conj(A) * d over this block's x window
        for (int i = t; i < 32 * 48; i += 256) {
            int ml = i / 48, c = i - ml * 48;
            int m  = mbase + kk + ml;
            float dr = g_dre[m], di = g_dim[m];
            float ar = g_Ar[m * NPIX + x0 + c];
            float ai = g_Ai[m * NPIX + x0 + c];
            sEr[ml][c] = fmaf(ar, dr,  ai * di);
            sEi[ml][c] = fmaf(ar, di, -ai * dr);
        }
        // stage B tile over this block's y window
        for (int i = t; i < 32 * 64; i += 256) {
            int ml = i / 64, c = i - ml * 64;
            int m  = mbase + kk + ml;
            sCr[ml][c] = g_Br[m * NPIX + y0 + c];
            sCi[ml][c] = g_Bi[m * NPIX + y0 + c];
        }
        __syncthreads();

#pragma unroll 4
        for (int k = 0; k < 32; ++k) {
            u64 brv[2], biv[2];
#pragma unroll
            for (int p = 0; p < 2; ++p) {
                int y = 2 * tx + 32 * p;
                brv[p] = *reinterpret_cast<const u64*>(&sCr[k][y]);
                biv[p] = *reinterpret_cast<const u64*>(&sCi[k][y]);
            }
#pragma unroll
            for (int a = 0; a < 3; ++a) {
                u64 per  = bc2(sEr[k][ty + 16 * a]);
                u64 pei  = bc2(sEi[k][ty + 16 * a]);
                u64 pner = per ^ SGN2;
#pragma unroll
                for (int p = 0; p < 2; ++p) {
                    // out += E * conj(B):
                    // re += er*br + ei*bi ; im += ei*br - er*bi
                    fma2(accr[a][p], per,  brv[p]);
                    fma2(accr[a][p], pei,  biv[p]);
                    fma2(acci[a][p], pei,  brv[p]);
                    fma2(acci[a][p], pner, biv[p]);
                }
            }
        }
        __syncthreads();
    }

    float* __restrict__ pp = g_part + blockIdx.z * (2 * NN);
#pragma unroll
    for (int a = 0; a < 3; ++a) {
        int x = x0 + ty + 16 * a;
#pragma unroll
        for (int p = 0; p < 2; ++p) {
            int y = y0 + 2 * tx + 32 * p;
            *reinterpret_cast<u64*>(&pp[x * NPIX + y])      = accr[a][p];
            *reinterpret_cast<u64*>(&pp[NN + x * NPIX + y]) = acci[a][p];
        }
    }
}

// -------------------- split-K reduce ------------------------------------------
__global__ void k_reduce(float* __restrict__ out, int mode) {
    int idx = blockIdx.x * blockDim.x + threadIdx.x;
    if (idx >= NN) return;
    float sr = 0.0f, si = 0.0f;
#pragma unroll 8
    for (int c = 0; c < NCHUNK; ++c) {
        sr += g_part[c * (2 * NN) + idx];
        si += g_part[c * (2 * NN) + NN + idx];
    }
    if (mode == 0) {
        int x = idx / NPIX, y = idx - (idx / NPIX) * NPIX;
        g_imgwT_re[y * NPIX + x] = sr;
        g_imgwT_im[y * NPIX + x] = si;
    } else {
        out[idx]      = sr;
        out[NN + idx] = si;
    }
}

// -------------------- driver ---------------------------------------------------
extern "C" void kernel_launch(void* const* d_in, const int* in_sizes, int n_in,
                              void* d_out, int out_size) {
    const float* xin  = (const float*)d_in[0];   // (2,192,192)
    const float* traj = (const float*)d_in[1];   // (36864,2)
    float* out = (float*)d_out;                  // (2,192,192)

    const int T = 256;
    k_build<<<(MPTS * NPIX + T - 1) / T, T>>>(traj);
    k_transpose_in<<<(NN + T - 1) / T, T>>>(xin);
    k_winit<<<(MPTS + T - 1) / T, T>>>();

    dim3 gadj(4, 3, NCHUNK);
    for (int it = 0; it < 3; ++it) {
        k_dfromw<<<(MPTS + T - 1) / T, T>>>();
        k_adj<<<gadj, 256>>>();
        k_reduce<<<(NN + T - 1) / T, T>>>(out, /*mode=*/0);
        k_op<<<MPTS / 16, 256>>>(/*src=*/1);
        k_wupdate<<<(MPTS + T - 1) / T, T>>>();
    }

    k_op<<<MPTS / 16, 256>>>(/*src=*/0);         // kspace = op(img)
    k_dscale<<<(MPTS + T - 1) / T, T>>>();       // d = w * kspace
    k_adj<<<gadj, 256>>>();
    k_reduce<<<(NN + T - 1) / T, T>>>(out, /*mode=*/1);
}

// round 9
// speedup vs baseline: 1.3322x; 1.3322x over previous
#include <cuda_runtime.h>
#include <cuda_bf16.h>
#include <math.h>
#include <stdint.h>

#define NPIX 192
#define MPTS 36864
#define NN   36864
#define KOP  1152          // 192*6 slots
#define KADJ 221184        // 36864*6 slots
#define TWO_PI_F 6.28318530717958647693f

typedef unsigned short u16;
typedef unsigned int   u32;

// ---------------- device globals ----------------
static __device__ __align__(16) u16 g_opA [(size_t)MPTS*KOP];    // 85MB
static __device__ __align__(16) u16 g_opBr[(size_t)NPIX*KOP];
static __device__ __align__(16) u16 g_opBi[(size_t)NPIX*KOP];
static __device__ __align__(16) u16 g_adjBr[(size_t)NPIX*KADJ];  // 85MB
static __device__ __align__(16) u16 g_adjBi[(size_t)NPIX*KADJ];  // 85MB
static __device__ __align__(16) u16 g_E[(size_t)NPIX*KADJ];      // 85MB
static __device__ float g_Amr[(size_t)MPTS*NPIX], g_Ami[(size_t)MPTS*NPIX];
static __device__ float g_Axr[(size_t)NPIX*MPTS], g_Axi[(size_t)NPIX*MPTS];
static __device__ float g_part[(size_t)144*NN];                  // 21MB
static __device__ float g_uv[4][MPTS];
static __device__ float g_w[MPTS], g_dre[MPTS], g_dim[MPTS], g_sre[MPTS], g_sim[MPTS];
static __device__ float g_pimg[2*NN];

// ---------------- helpers ----------------
__device__ __forceinline__ void splitbf(float v,u16&h,u16&l){
    __nv_bfloat16 a=__float2bfloat16_rn(v);
    __nv_bfloat16 b=__float2bfloat16_rn(v-__bfloat162float(a));
    h=__bfloat16_as_ushort(a); l=__bfloat16_as_ushort(b);
}
__device__ __forceinline__ void hmma(float* c,u32 a0,u32 a1,u32 a2,u32 a3,u32 b0,u32 b1){
    asm volatile("mma.sync.aligned.m16n8k16.row.col.f32.bf16.bf16.f32 {%0,%1,%2,%3},{%4,%5,%6,%7},{%8,%9},{%0,%1,%2,%3};"
        : "+f"(c[0]),"+f"(c[1]),"+f"(c[2]),"+f"(c[3])
        : "r"(a0),"r"(a1),"r"(a2),"r"(a3),"r"(b0),"r"(b1));
}

// ---------------- GEMM core: M=192, N=192, K-chunk = 48 slots ----------------
// smem: A tile 192 rows x 112B (48 u16 data + pad) = 21504B; B tile same at +21504.
// Total 43008B (< 48KB -> no smem opt-in needed). Synchronous staging.
__device__ __forceinline__ void stage_sync(char* sm,const u16* gA,size_t sA,
                                           const u16* gB,size_t sB,int ch){
    int t = threadIdx.x;
    int r = t >> 1, half = t & 1;          // 192 rows, 2 threads per row
    const uint4* srcA = (const uint4*)(gA + (size_t)ch*48 + (size_t)r*sA);
    const uint4* srcB = (const uint4*)(gB + (size_t)ch*48 + (size_t)r*sB);
    uint4* dstA = (uint4*)(sm + r*112);
    uint4* dstB = (uint4*)(sm + 21504 + r*112);
#pragma unroll
    for(int q=0;q<3;++q){
        int c4 = half*3 + q;               // 6 uint4 per 96B row
        dstA[c4] = srcA[c4];
        dstB[c4] = srcB[c4];
    }
}
// Direct m16n8k16 fragment loads (lane = 4*g + j3):
//   a0=A[g][2j3] a1=A[g+8][2j3] a2=A[g][2j3+8] a3=A[g+8][2j3+8]
//   b0=Bst[n=g][2j3] b1=Bst[n=g][2j3+8]   (Bst is [n][k], k contiguous)
__device__ __forceinline__ void compute192(const char* sm,float* acc){
    int lane = threadIdx.x & 31, w = threadIdx.x >> 5;
    int g = lane>>2, j3 = lane&3;
    const u16* A = (const u16*)sm;
    const u16* B = (const u16*)(sm + 21504);
    int rA0 = (w*16+g)*56, rA1 = rA0 + 8*56;     // row stride 56 u16 = 112B
#pragma unroll
    for(int s=0;s<3;++s){
        int c0 = s*16 + 2*j3;
        u32 a0 = *(const u32*)&A[rA0 + c0];
        u32 a1 = *(const u32*)&A[rA1 + c0];
        u32 a2 = *(const u32*)&A[rA0 + c0 + 8];
        u32 a3 = *(const u32*)&A[rA1 + c0 + 8];
#pragma unroll
        for(int tp=0;tp<12;++tp){
            int rB0 = (tp*16+g)*56, rB1 = rB0 + 8*56;
            u32 b0 = *(const u32*)&B[rB0 + c0];
            u32 b1 = *(const u32*)&B[rB0 + c0 + 8];
            u32 b2 = *(const u32*)&B[rB1 + c0];
            u32 b3 = *(const u32*)&B[rB1 + c0 + 8];
            hmma(acc + (2*tp)*4,   a0,a1,a2,a3, b0,b1);
            hmma(acc + (2*tp+1)*4, a0,a1,a2,a3, b2,b3);
        }
    }
}
__device__ __forceinline__ void gemm192(const u16* gA,size_t sA,const u16* gB,size_t sB,
                                        int nch,char* sm,float* acc){
    for(int c=0;c<nch;++c){
        __syncthreads();                   // previous compute done before overwrite
        stage_sync(sm,gA,sA,gB,sB,c);
        __syncthreads();
        compute192(sm,acc);
    }
}

// ---------------- builds ----------------
__global__ void k_build_ky(const float* __restrict__ traj){
    int m = blockIdx.x*256 + threadIdx.x;
    int oct = blockIdx.y;
    float ky = traj[2*m+1];
    float ph = ky*(float)(oct*8-96); float r = ph-rintf(ph);
    float s,c; __sincosf(-TWO_PI_F*r,&s,&c);
    float su,cu; __sincosf(-TWO_PI_F*ky,&su,&cu);
    for(int i=0;i<8;++i){
        int y = oct*8+i;
        u16 ch,cl,sh,sl; splitbf(c,ch,cl); splitbf(s,sh,sl);
        u32* pa = (u32*)(g_opA + (size_t)m*KOP + 6*y);
        pa[0]=(u32)ch|((u32)ch<<16); pa[1]=(u32)cl|((u32)sh<<16); pa[2]=(u32)sh|((u32)sl<<16);
        u32* pr = (u32*)(g_adjBr + (size_t)y*KADJ + 6*m);
        pr[0]=(u32)ch|((u32)cl<<16); pr[1]=(u32)ch|((u32)sh<<16); pr[2]=(u32)sl|((u32)sh<<16);
        u16 nh=sh^0x8000, nl=sl^0x8000;
        u32* pi = (u32*)(g_adjBi + (size_t)y*KADJ + 6*m);
        pi[0]=(u32)nh|((u32)nl<<16); pi[1]=(u32)nh|((u32)ch<<16); pi[2]=(u32)cl|((u32)ch<<16);
        float nc = c*cu - s*su; s = s*cu + c*su; c = nc;
    }
}
__global__ void k_build_kx(const float* __restrict__ traj){
    int m = blockIdx.x*256 + threadIdx.x;
    int oct = blockIdx.y;
    float kx = traj[2*m];
    float ph = kx*(float)(oct*8-96); float r = ph-rintf(ph);
    float s,c; __sincosf(-TWO_PI_F*r,&s,&c);
    float su,cu; __sincosf(-TWO_PI_F*kx,&su,&cu);
    for(int i=0;i<8;++i){
        int x = oct*8+i;
        g_Amr[(size_t)m*NPIX+x]=c; g_Ami[(size_t)m*NPIX+x]=s;
        g_Axr[(size_t)x*MPTS+m]=c; g_Axi[(size_t)x*MPTS+m]=s;
        float nc = c*cu - s*su; s = s*cu + c*su; c = nc;
    }
}
__global__ void k_opB(const float* __restrict__ xin, int usePipe){
    int idx = blockIdx.x*256 + threadIdx.x;
    int x = idx/192, y = idx - x*192;
    float re = usePipe ? g_pimg[idx] : xin[idx];
    float im = usePipe ? g_pimg[NN+idx] : xin[NN+idx];
    u16 rh,rl,ih,il; splitbf(re,rh,rl); splitbf(im,ih,il);
    u16 nh=ih^0x8000, nl=il^0x8000;
    u32* pr = (u32*)(g_opBr + (size_t)x*KOP + 6*y);
    pr[0]=(u32)rh|((u32)rl<<16); pr[1]=(u32)rh|((u32)nh<<16); pr[2]=(u32)nl|((u32)nh<<16);
    u32* pi = (u32*)(g_opBi + (size_t)x*KOP + 6*y);
    pi[0]=(u32)ih|((u32)il<<16); pi[1]=(u32)ih|((u32)rh<<16); pi[2]=(u32)rl|((u32)rh<<16);
}
__global__ void k_Ebuild(){
    int m = blockIdx.x*256 + threadIdx.x;
    int x = blockIdx.y;
    float dr=g_dre[m], di=g_dim[m];
    float ar=g_Axr[(size_t)x*MPTS+m], ai=g_Axi[(size_t)x*MPTS+m];
    float er = ar*dr + ai*di, ei = ar*di - ai*dr;
    u16 eh,el,fh,fl; splitbf(er,eh,el); splitbf(ei,fh,fl);
    u32* p = (u32*)(g_E + (size_t)x*KADJ + 6*m);
    p[0]=(u32)eh|((u32)eh<<16); p[1]=(u32)el|((u32)fh<<16); p[2]=(u32)fh|((u32)fl<<16);
}

// ---------------- elementwise ----------------
__global__ void k_winit(){int i=blockIdx.x*256+threadIdx.x; g_w[i]=1.0f;}
__global__ void k_dfromw(){int i=blockIdx.x*256+threadIdx.x; g_dre[i]=g_w[i]; g_dim[i]=0.0f;}
__global__ void k_wupdate(){int i=blockIdx.x*256+threadIdx.x;
    float m=sqrtf(g_sre[i]*g_sre[i]+g_sim[i]*g_sim[i]); g_w[i]=g_w[i]/fmaxf(m,1e-20f);}
__global__ void k_dscale(){int i=blockIdx.x*256+threadIdx.x;
    g_dre[i]=g_w[i]*g_sre[i]; g_dim[i]=g_w[i]*g_sim[i];}
__global__ void k_scomb(){int i=blockIdx.x*256+threadIdx.x;
    g_sre[i]=g_uv[0][i]-g_uv[3][i]; g_sim[i]=g_uv[2][i]+g_uv[1][i];}
__global__ void k_reduce(float* __restrict__ out, int mode){
    int idx = blockIdx.x*256 + threadIdx.x;     // 0..73727
    int c = idx >= NN;
    int xy = idx - (c?NN:0);
    float s = 0.f;
#pragma unroll 8
    for(int z=0;z<72;++z) s += g_part[((size_t)(c*72+z))*NN + xy];
    if(mode) out[idx]=s; else g_pimg[idx]=s;
}

// ---------------- op GEMM: T[m,x] + fused A-dot partials ---------------------
__global__ void __launch_bounds__(384) k_opg(){
    extern __shared__ char dsm[];
    float acc[96];
#pragma unroll
    for(int i=0;i<96;++i) acc[i]=0.f;
    int blk = blockIdx.x, var = blockIdx.y;
    const u16* gA = g_opA + (size_t)blk*192*KOP;
    const u16* gB = var ? g_opBi : g_opBr;
    gemm192(gA, KOP, gB, KOP, 24, dsm, acc);

    int lane = threadIdx.x&31, w = threadIdx.x>>5;
    int g = lane>>2, j3 = lane&3;
    int mA = blk*192 + w*16 + g, mB = mA+8;
    float u1a=0,u2a=0,u1b=0,u2b=0;
#pragma unroll
    for(int tp=0;tp<24;++tp){
        int x = tp*8 + j3*2;
        float ar0=__ldg(&g_Amr[(size_t)mA*NPIX+x]), ar1=__ldg(&g_Amr[(size_t)mA*NPIX+x+1]);
        float ai0=__ldg(&g_Ami[(size_t)mA*NPIX+x]), ai1=__ldg(&g_Ami[(size_t)mA*NPIX+x+1]);
        u1a += ar0*acc[tp*4+0] + ar1*acc[tp*4+1];
        u2a += ai0*acc[tp*4+0] + ai1*acc[tp*4+1];
        float br0=__ldg(&g_Amr[(size_t)mB*NPIX+x]), br1=__ldg(&g_Amr[(size_t)mB*NPIX+x+1]);
        float bi0=__ldg(&g_Ami[(size_t)mB*NPIX+x]), bi1=__ldg(&g_Ami[(size_t)mB*NPIX+x+1]);
        u1b += br0*acc[tp*4+2] + br1*acc[tp*4+3];
        u2b += bi0*acc[tp*4+2] + bi1*acc[tp*4+3];
    }
#pragma unroll
    for(int o=1;o<4;o<<=1){
        u1a += __shfl_xor_sync(0xffffffffu,u1a,o);
        u2a += __shfl_xor_sync(0xffffffffu,u2a,o);
        u1b += __shfl_xor_sync(0xffffffffu,u1b,o);
        u2b += __shfl_xor_sync(0xffffffffu,u2b,o);
    }
    if(j3==0){
        float* d1 = var ? g_uv[2] : g_uv[0];
        float* d2 = var ? g_uv[3] : g_uv[1];
        d1[mA]=u1a; d2[mA]=u2a; d1[mB]=u1b; d2[mB]=u2b;
    }
}

// ---------------- adj GEMM: split-K partials ---------------------------------
__global__ void __launch_bounds__(384) k_adjg(){
    extern __shared__ char dsm[];
    float acc[96];
#pragma unroll
    for(int i=0;i<96;++i) acc[i]=0.f;
    int z = blockIdx.x, var = blockIdx.y;
    const u16* gA = g_E + (size_t)z*3072;
    const u16* gB = (var ? g_adjBi : g_adjBr) + (size_t)z*3072;
    gemm192(gA, KADJ, gB, KADJ, 64, dsm, acc);

    int lane = threadIdx.x&31, w = threadIdx.x>>5;
    int g = lane>>2, j3 = lane&3;
    float* pp = g_part + ((size_t)var*72 + z)*NN;
    int xA = w*16 + g, xB = xA+8;
#pragma unroll
    for(int tp=0;tp<24;++tp){
        int y = tp*8 + j3*2;
        *(float2*)&pp[(size_t)xA*192+y] = make_float2(acc[tp*4+0],acc[tp*4+1]);
        *(float2*)&pp[(size_t)xB*192+y] = make_float2(acc[tp*4+2],acc[tp*4+3]);
    }
}

// ---------------- driver ----------------
extern "C" void kernel_launch(void* const* d_in, const int* in_sizes, int n_in,
                              void* d_out, int out_size) {
    const float* xin  = (const float*)d_in[0];
    const float* traj = (const float*)d_in[1];
    float* out = (float*)d_out;
    const int SMEM = 43008;      // < 48KB: no attribute opt-in required

    dim3 gb(144,24);
    k_build_ky<<<gb,256>>>(traj);
    k_build_kx<<<gb,256>>>(traj);
    k_winit<<<144,256>>>();

    for(int it=0; it<3; ++it){
        k_dfromw<<<144,256>>>();
        k_Ebuild<<<dim3(144,192),256>>>();
        k_adjg<<<dim3(72,2),384,SMEM>>>();
        k_reduce<<<288,256>>>(out,0);
        k_opB<<<144,256>>>(xin,1);
        k_opg<<<dim3(192,2),384,SMEM>>>();
        k_scomb<<<144,256>>>();
        k_wupdate<<<144,256>>>();
    }
    k_opB<<<144,256>>>(xin,0);
    k_opg<<<dim3(192,2),384,SMEM>>>();
    k_scomb<<<144,256>>>();
    k_dscale<<<144,256>>>();
    k_Ebuild<<<dim3(144,192),256>>>();
    k_adjg<<<dim3(72,2),384,SMEM>>>();
    k_reduce<<<288,256>>>(out,1);
}

// round 10
// speedup vs baseline: 1.3699x; 1.0283x over previous
#include <cuda_runtime.h>
#include <cuda_bf16.h>
#include <math.h>
#include <stdint.h>

#define NPIX 192
#define MPTS 36864
#define NN   36864
#define KOP  1152          // 192*6 slots
#define KADJ 221184        // 36864*6 slots
#define TWO_PI_F 6.28318530717958647693f

typedef unsigned short u16;
typedef unsigned int   u32;

// ---------------- device globals ----------------
static __device__ __align__(16) u16 g_opA [(size_t)MPTS*KOP];    // 85MB
static __device__ __align__(16) u16 g_opBr[(size_t)NPIX*KOP];
static __device__ __align__(16) u16 g_opBi[(size_t)NPIX*KOP];
static __device__ __align__(16) u16 g_adjBr[(size_t)NPIX*KADJ];  // 85MB
static __device__ __align__(16) u16 g_adjBi[(size_t)NPIX*KADJ];  // 85MB
static __device__ __align__(16) u16 g_E[(size_t)NPIX*KADJ];      // 85MB
static __device__ float g_Amr[(size_t)MPTS*NPIX], g_Ami[(size_t)MPTS*NPIX];
static __device__ float g_Axr[(size_t)NPIX*MPTS], g_Axi[(size_t)NPIX*MPTS];
static __device__ float g_part[(size_t)144*NN];                  // 21MB
static __device__ float g_uv[4][MPTS];
static __device__ float g_w[MPTS], g_dre[MPTS], g_dim[MPTS], g_sre[MPTS], g_sim[MPTS];
static __device__ float g_pimg[2*NN];

// ---------------- helpers ----------------
__device__ __forceinline__ void splitbf(float v,u16&h,u16&l){
    __nv_bfloat16 a=__float2bfloat16_rn(v);
    __nv_bfloat16 b=__float2bfloat16_rn(v-__bfloat162float(a));
    h=__bfloat16_as_ushort(a); l=__bfloat16_as_ushort(b);
}
__device__ __forceinline__ void hmma(float* c,u32 a0,u32 a1,u32 a2,u32 a3,u32 b0,u32 b1){
    asm volatile("mma.sync.aligned.m16n8k16.row.col.f32.bf16.bf16.f32 {%0,%1,%2,%3},{%4,%5,%6,%7},{%8,%9},{%0,%1,%2,%3};"
        : "+f"(c[0]),"+f"(c[1]),"+f"(c[2]),"+f"(c[3])
        : "r"(a0),"r"(a1),"r"(a2),"r"(a3),"r"(b0),"r"(b1));
}

// ---------------- GEMM core: M=192, N=192, K-chunk = 48 slots ----------------
// smem: A tile 192 rows x 112B (48 u16 + pad); B tile same at +21504. 43008B total.
// Register-pipelined: LDG chunk c+1 into regs, compute chunk c, then STS.
__device__ __forceinline__ void compute192(const char* sm,float* acc){
    int lane = threadIdx.x & 31, w = threadIdx.x >> 5;
    int g = lane>>2, j3 = lane&3;
    const u16* A = (const u16*)sm;
    const u16* B = (const u16*)(sm + 21504);
    int rA0 = (w*16+g)*56, rA1 = rA0 + 8*56;     // row stride 56 u16 = 112B
#pragma unroll
    for(int s=0;s<3;++s){
        int c0 = s*16 + 2*j3;
        u32 a0 = *(const u32*)&A[rA0 + c0];
        u32 a1 = *(const u32*)&A[rA1 + c0];
        u32 a2 = *(const u32*)&A[rA0 + c0 + 8];
        u32 a3 = *(const u32*)&A[rA1 + c0 + 8];
#pragma unroll
        for(int tp=0;tp<12;++tp){
            int rB0 = (tp*16+g)*56, rB1 = rB0 + 8*56;
            u32 b0 = *(const u32*)&B[rB0 + c0];
            u32 b1 = *(const u32*)&B[rB0 + c0 + 8];
            u32 b2 = *(const u32*)&B[rB1 + c0];
            u32 b3 = *(const u32*)&B[rB1 + c0 + 8];
            hmma(acc + (2*tp)*4,   a0,a1,a2,a3, b0,b1);
            hmma(acc + (2*tp+1)*4, a0,a1,a2,a3, b2,b3);
        }
    }
}
__device__ __forceinline__ void gemm192(const u16* gA,size_t sA,const u16* gB,size_t sB,
                                        int nch,char* sm,float* acc){
    int r = threadIdx.x >> 1, half = threadIdx.x & 1;
    uint4* dstA = (uint4*)(sm + r*112) + half*3;
    uint4* dstB = (uint4*)(sm + 21504 + r*112) + half*3;

    // prologue: stage chunk 0
    {
        const uint4* srcA = (const uint4*)(gA + (size_t)r*sA) + half*3;
        const uint4* srcB = (const uint4*)(gB + (size_t)r*sB) + half*3;
#pragma unroll
        for(int q=0;q<3;++q){ dstA[q]=srcA[q]; dstB[q]=srcB[q]; }
    }
    __syncthreads();

    for(int c=0;c<nch;++c){
        uint4 ra[3], rb[3];
        if(c+1<nch){
            const uint4* srcA = (const uint4*)(gA + (size_t)(c+1)*48 + (size_t)r*sA) + half*3;
            const uint4* srcB = (const uint4*)(gB + (size_t)(c+1)*48 + (size_t)r*sB) + half*3;
#pragma unroll
            for(int q=0;q<3;++q){ ra[q]=srcA[q]; rb[q]=srcB[q]; }   // LDG in flight
        }
        compute192(sm,acc);                                          // overlaps LDG
        if(c+1<nch){
            __syncthreads();                                         // compute done
#pragma unroll
            for(int q=0;q<3;++q){ dstA[q]=ra[q]; dstB[q]=rb[q]; }
            __syncthreads();                                         // stores visible
        }
    }
}

// ---------------- builds ----------------
__global__ void k_build_ky(const float* __restrict__ traj){
    int m = blockIdx.x*256 + threadIdx.x;
    int oct = blockIdx.y;
    float ky = traj[2*m+1];
    float ph = ky*(float)(oct*8-96); float r = ph-rintf(ph);
    float s,c; __sincosf(-TWO_PI_F*r,&s,&c);
    float su,cu; __sincosf(-TWO_PI_F*ky,&su,&cu);
    for(int i=0;i<8;++i){
        int y = oct*8+i;
        u16 ch,cl,sh,sl; splitbf(c,ch,cl); splitbf(s,sh,sl);
        u32* pa = (u32*)(g_opA + (size_t)m*KOP + 6*y);
        pa[0]=(u32)ch|((u32)ch<<16); pa[1]=(u32)cl|((u32)sh<<16); pa[2]=(u32)sh|((u32)sl<<16);
        u32* pr = (u32*)(g_adjBr + (size_t)y*KADJ + 6*m);
        pr[0]=(u32)ch|((u32)cl<<16); pr[1]=(u32)ch|((u32)sh<<16); pr[2]=(u32)sl|((u32)sh<<16);
        u16 nh=sh^0x8000, nl=sl^0x8000;
        u32* pi = (u32*)(g_adjBi + (size_t)y*KADJ + 6*m);
        pi[0]=(u32)nh|((u32)nl<<16); pi[1]=(u32)nh|((u32)ch<<16); pi[2]=(u32)cl|((u32)ch<<16);
        float nc = c*cu - s*su; s = s*cu + c*su; c = nc;
    }
}
__global__ void k_build_kx(const float* __restrict__ traj){
    int m = blockIdx.x*256 + threadIdx.x;
    int oct = blockIdx.y;
    float kx = traj[2*m];
    float ph = kx*(float)(oct*8-96); float r = ph-rintf(ph);
    float s,c; __sincosf(-TWO_PI_F*r,&s,&c);
    float su,cu; __sincosf(-TWO_PI_F*kx,&su,&cu);
    for(int i=0;i<8;++i){
        int x = oct*8+i;
        g_Amr[(size_t)m*NPIX+x]=c; g_Ami[(size_t)m*NPIX+x]=s;
        g_Axr[(size_t)x*MPTS+m]=c; g_Axi[(size_t)x*MPTS+m]=s;
        float nc = c*cu - s*su; s = s*cu + c*su; c = nc;
    }
}
__global__ void k_opB(const float* __restrict__ xin, int usePipe){
    int idx = blockIdx.x*256 + threadIdx.x;
    int x = idx/192, y = idx - x*192;
    float re = usePipe ? g_pimg[idx] : xin[idx];
    float im = usePipe ? g_pimg[NN+idx] : xin[NN+idx];
    u16 rh,rl,ih,il; splitbf(re,rh,rl); splitbf(im,ih,il);
    u16 nh=ih^0x8000, nl=il^0x8000;
    u32* pr = (u32*)(g_opBr + (size_t)x*KOP + 6*y);
    pr[0]=(u32)rh|((u32)rl<<16); pr[1]=(u32)rh|((u32)nh<<16); pr[2]=(u32)nl|((u32)nh<<16);
    u32* pi = (u32*)(g_opBi + (size_t)x*KOP + 6*y);
    pi[0]=(u32)ih|((u32)il<<16); pi[1]=(u32)ih|((u32)rh<<16); pi[2]=(u32)rl|((u32)rh<<16);
}
__global__ void k_Ebuild(){
    int m = blockIdx.x*256 + threadIdx.x;
    int x = blockIdx.y;
    float dr=g_dre[m], di=g_dim[m];
    float ar=g_Axr[(size_t)x*MPTS+m], ai=g_Axi[(size_t)x*MPTS+m];
    float er = ar*dr + ai*di, ei = ar*di - ai*dr;
    u16 eh,el,fh,fl; splitbf(er,eh,el); splitbf(ei,fh,fl);
    u32* p = (u32*)(g_E + (size_t)x*KADJ + 6*m);
    p[0]=(u32)eh|((u32)eh<<16); p[1]=(u32)el|((u32)fh<<16); p[2]=(u32)fh|((u32)fl<<16);
}

// ---------------- elementwise ----------------
__global__ void k_winit(){int i=blockIdx.x*256+threadIdx.x; g_w[i]=1.0f;}
__global__ void k_dfromw(){int i=blockIdx.x*256+threadIdx.x; g_dre[i]=g_w[i]; g_dim[i]=0.0f;}
__global__ void k_wupdate(){int i=blockIdx.x*256+threadIdx.x;
    float m=sqrtf(g_sre[i]*g_sre[i]+g_sim[i]*g_sim[i]); g_w[i]=g_w[i]/fmaxf(m,1e-20f);}
__global__ void k_dscale(){int i=blockIdx.x*256+threadIdx.x;
    g_dre[i]=g_w[i]*g_sre[i]; g_dim[i]=g_w[i]*g_sim[i];}
__global__ void k_scomb(){int i=blockIdx.x*256+threadIdx.x;
    g_sre[i]=g_uv[0][i]-g_uv[3][i]; g_sim[i]=g_uv[2][i]+g_uv[1][i];}
__global__ void k_reduce(float* __restrict__ out, int mode){
    int idx = blockIdx.x*256 + threadIdx.x;     // 0..73727
    int c = idx >= NN;
    int xy = idx - (c?NN:0);
    float s = 0.f;
#pragma unroll 8
    for(int z=0;z<72;++z) s += g_part[((size_t)(c*72+z))*NN + xy];
    if(mode) out[idx]=s; else g_pimg[idx]=s;
}

// ---------------- op GEMM: T[m,x] + fused A-dot partials ---------------------
__global__ void __launch_bounds__(384) k_opg(){
    extern __shared__ char dsm[];
    float acc[96];
#pragma unroll
    for(int i=0;i<96;++i) acc[i]=0.f;
    int blk = blockIdx.x, var = blockIdx.y;
    const u16* gA = g_opA + (size_t)blk*192*KOP;
    const u16* gB = var ? g_opBi : g_opBr;
    gemm192(gA, KOP, gB, KOP, 24, dsm, acc);

    int lane = threadIdx.x&31, w = threadIdx.x>>5;
    int g = lane>>2, j3 = lane&3;
    int mA = blk*192 + w*16 + g, mB = mA+8;
    float u1a=0,u2a=0,u1b=0,u2b=0;
#pragma unroll
    for(int tp=0;tp<24;++tp){
        int x = tp*8 + j3*2;
        float ar0=__ldg(&g_Amr[(size_t)mA*NPIX+x]), ar1=__ldg(&g_Amr[(size_t)mA*NPIX+x+1]);
        float ai0=__ldg(&g_Ami[(size_t)mA*NPIX+x]), ai1=__ldg(&g_Ami[(size_t)mA*NPIX+x+1]);
        u1a += ar0*acc[tp*4+0] + ar1*acc[tp*4+1];
        u2a += ai0*acc[tp*4+0] + ai1*acc[tp*4+1];
        float br0=__ldg(&g_Amr[(size_t)mB*NPIX+x]), br1=__ldg(&g_Amr[(size_t)mB*NPIX+x+1]);
        float bi0=__ldg(&g_Ami[(size_t)mB*NPIX+x]), bi1=__ldg(&g_Ami[(size_t)mB*NPIX+x+1]);
        u1b += br0*acc[tp*4+2] + br1*acc[tp*4+3];
        u2b += bi0*acc[tp*4+2] + bi1*acc[tp*4+3];
    }
#pragma unroll
    for(int o=1;o<4;o<<=1){
        u1a += __shfl_xor_sync(0xffffffffu,u1a,o);
        u2a += __shfl_xor_sync(0xffffffffu,u2a,o);
        u1b += __shfl_xor_sync(0xffffffffu,u1b,o);
        u2b += __shfl_xor_sync(0xffffffffu,u2b,o);
    }
    if(j3==0){
        float* d1 = var ? g_uv[2] : g_uv[0];
        float* d2 = var ? g_uv[3] : g_uv[1];
        d1[mA]=u1a; d2[mA]=u2a; d1[mB]=u1b; d2[mB]=u2b;
    }
}

// ---------------- adj GEMM: split-K partials ---------------------------------
__global__ void __launch_bounds__(384) k_adjg(){
    extern __shared__ char dsm[];
    float acc[96];
#pragma unroll
    for(int i=0;i<96;++i) acc[i]=0.f;
    int z = blockIdx.x, var = blockIdx.y;
    const u16* gA = g_E + (size_t)z*3072;
    const u16* gB = (var ? g_adjBi : g_adjBr) + (size_t)z*3072;
    gemm192(gA, KADJ, gB, KADJ, 64, dsm, acc);

    int lane = threadIdx.x&31, w = threadIdx.x>>5;
    int g = lane>>2, j3 = lane&3;
    float* pp = g_part + ((size_t)var*72 + z)*NN;
    int xA = w*16 + g, xB = xA+8;
#pragma unroll
    for(int tp=0;tp<24;++tp){
        int y = tp*8 + j3*2;
        *(float2*)&pp[(size_t)xA*192+y] = make_float2(acc[tp*4+0],acc[tp*4+1]);
        *(float2*)&pp[(size_t)xB*192+y] = make_float2(acc[tp*4+2],acc[tp*4+3]);
    }
}

// ---------------- driver ----------------
extern "C" void kernel_launch(void* const* d_in, const int* in_sizes, int n_in,
                              void* d_out, int out_size) {
    const float* xin  = (const float*)d_in[0];
    const float* traj = (const float*)d_in[1];
    float* out = (float*)d_out;
    const int SMEM = 43008;      // < 48KB: no attribute opt-in required

    dim3 gb(144,24);
    k_build_ky<<<gb,256>>>(traj);
    k_build_kx<<<gb,256>>>(traj);
    k_winit<<<144,256>>>();

    for(int it=0; it<3; ++it){
        k_dfromw<<<144,256>>>();
        k_Ebuild<<<dim3(144,192),256>>>();
        k_adjg<<<dim3(72,2),384,SMEM>>>();
        k_reduce<<<288,256>>>(out,0);
        k_opB<<<144,256>>>(xin,1);
        k_opg<<<dim3(192,2),384,SMEM>>>();
        k_scomb<<<144,256>>>();
        k_wupdate<<<144,256>>>();
    }
    k_opB<<<144,256>>>(xin,0);
    k_opg<<<dim3(192,2),384,SMEM>>>();
    k_scomb<<<144,256>>>();
    k_dscale<<<144,256>>>();
    k_Ebuild<<<dim3(144,192),256>>>();
    k_adjg<<<dim3(72,2),384,SMEM>>>();
    k_reduce<<<288,256>>>(out,1);
}

// round 11
// speedup vs baseline: 1.7091x; 1.2476x over previous
#include <cuda_runtime.h>
#include <cuda_bf16.h>
#include <math.h>
#include <stdint.h>

#define NPIX 192
#define MPTS 36864
#define NN   36864
#define KOP  1152          // 192*6 slots
#define KADJ 221184        // 36864*6 slots
#define TWO_PI_F 6.28318530717958647693f

typedef unsigned short u16;
typedef unsigned int   u32;

// ---------------- device globals ----------------
static __device__ __align__(16) u16 g_opA [(size_t)MPTS*KOP];    // 85MB
static __device__ __align__(16) u16 g_opBr[(size_t)NPIX*KOP];
static __device__ __align__(16) u16 g_opBi[(size_t)NPIX*KOP];
static __device__ __align__(16) u16 g_adjBr[(size_t)NPIX*KADJ];  // 85MB
static __device__ __align__(16) u16 g_adjBi[(size_t)NPIX*KADJ];  // 85MB
static __device__ __align__(16) u16 g_E[(size_t)NPIX*KADJ];      // 85MB
static __device__ float g_Amr[(size_t)MPTS*NPIX], g_Ami[(size_t)MPTS*NPIX];
static __device__ float g_Axr[(size_t)NPIX*MPTS], g_Axi[(size_t)NPIX*MPTS];
static __device__ float g_part[(size_t)144*NN];                  // 21MB
static __device__ float g_uv[4][MPTS];
static __device__ float g_w[MPTS], g_dre[MPTS], g_dim[MPTS], g_sre[MPTS], g_sim[MPTS];
static __device__ float g_pimg[2*NN];

// ---------------- helpers ----------------
__device__ __forceinline__ u32 s2u(const void* p){u32 a;asm("{ .reg .u64 t; cvta.to.shared.u64 t, %1; cvt.u32.u64 %0, t; }":"=r"(a):"l"(p));return a;}
__device__ __forceinline__ void splitbf(float v,u16&h,u16&l){
    __nv_bfloat16 a=__float2bfloat16_rn(v);
    __nv_bfloat16 b=__float2bfloat16_rn(v-__bfloat162float(a));
    h=__bfloat16_as_ushort(a); l=__bfloat16_as_ushort(b);
}
__device__ __forceinline__ void hmma(float* c,u32 a0,u32 a1,u32 a2,u32 a3,u32 b0,u32 b1){
    asm volatile("mma.sync.aligned.m16n8k16.row.col.f32.bf16.bf16.f32 {%0,%1,%2,%3},{%4,%5,%6,%7},{%8,%9},{%0,%1,%2,%3};"
        : "+f"(c[0]),"+f"(c[1]),"+f"(c[2]),"+f"(c[3])
        : "r"(a0),"r"(a1),"r"(a2),"r"(a3),"r"(b0),"r"(b1));
}
#define LDMX4(r0,r1,r2,r3,addr) \
    asm volatile("ldmatrix.sync.aligned.m8n8.x4.shared.b16 {%0,%1,%2,%3},[%4];" \
        : "=r"(r0),"=r"(r1),"=r"(r2),"=r"(r3) : "r"(addr))

// ---------------- GEMM core: M=192, N=192, K-chunk = 48 slots ----------------
// smem: A tile 192 rows x 112B (48 u16 + pad); B tile same at +21504. 43008B.
// Warp grid 4(m) x 3(n): warp owns m=48, n=64 -> per-chunk crossbar traffic
// 129KB (vs 239KB for 12x full-N). ldmatrix.x4 for all fragments.
__device__ __forceinline__ void compute192(const char* sm,float* acc){
    int lane = threadIdx.x & 31, w = threadIdx.x >> 5;
    int wm = w & 3, wn = w >> 2;                 // m-tile 48, n-tile 64
    int q = lane & 7, quad = lane >> 3;
    u32 smu = s2u(sm);
    // A matrices: M0=(r,c) M1=(r+8,c) M2=(r,c+8) M3=(r+8,c+8)
    u32 aAddr0 = smu + (u32)((wm*48 + (quad&1)*8 + q)*112 + ((quad>>1)*8)*2);
    // B matrices: M0=(n,c) M1=(n,c+8) M2=(n+8,c) M3=(n+8,c+8)
    u32 bAddr0 = smu + 21504u + (u32)((wn*64 + ((quad>>1)&1)*8 + q)*112 + ((quad&1)*8)*2);
#pragma unroll
    for(int s=0;s<3;++s){
        u32 a[3][4];
#pragma unroll
        for(int mg=0;mg<3;++mg)
            LDMX4(a[mg][0],a[mg][1],a[mg][2],a[mg][3], aAddr0 + (u32)(mg*16*112 + s*32));
#pragma unroll
        for(int ng=0;ng<4;++ng){
            u32 b0,b1,b2,b3;
            LDMX4(b0,b1,b2,b3, bAddr0 + (u32)(ng*16*112 + s*32));
#pragma unroll
            for(int mg=0;mg<3;++mg){
                hmma(acc + (mg*8 + ng*2    )*4, a[mg][0],a[mg][1],a[mg][2],a[mg][3], b0,b1);
                hmma(acc + (mg*8 + ng*2 + 1)*4, a[mg][0],a[mg][1],a[mg][2],a[mg][3], b2,b3);
            }
        }
    }
}
__device__ __forceinline__ void gemm192(const u16* gA,size_t sA,const u16* gB,size_t sB,
                                        int nch,char* sm,float* acc){
    int r = threadIdx.x >> 1, half = threadIdx.x & 1;
    uint4* dstA = (uint4*)(sm + r*112) + half*3;
    uint4* dstB = (uint4*)(sm + 21504 + r*112) + half*3;
    {
        const uint4* srcA = (const uint4*)(gA + (size_t)r*sA) + half*3;
        const uint4* srcB = (const uint4*)(gB + (size_t)r*sB) + half*3;
#pragma unroll
        for(int q=0;q<3;++q){ dstA[q]=srcA[q]; dstB[q]=srcB[q]; }
    }
    __syncthreads();
    for(int c=0;c<nch;++c){
        uint4 ra[3], rb[3];
        if(c+1<nch){
            const uint4* srcA = (const uint4*)(gA + (size_t)(c+1)*48 + (size_t)r*sA) + half*3;
            const uint4* srcB = (const uint4*)(gB + (size_t)(c+1)*48 + (size_t)r*sB) + half*3;
#pragma unroll
            for(int q=0;q<3;++q){ ra[q]=srcA[q]; rb[q]=srcB[q]; }
        }
        compute192(sm,acc);
        if(c+1<nch){
            __syncthreads();
#pragma unroll
            for(int q=0;q<3;++q){ dstA[q]=ra[q]; dstB[q]=rb[q]; }
            __syncthreads();
        }
    }
}

// ---------------- builds ----------------
__global__ void k_build_ky(const float* __restrict__ traj){
    int m = blockIdx.x*256 + threadIdx.x;
    int oct = blockIdx.y;
    float ky = traj[2*m+1];
    float ph = ky*(float)(oct*8-96); float r = ph-rintf(ph);
    float s,c; __sincosf(-TWO_PI_F*r,&s,&c);
    float su,cu; __sincosf(-TWO_PI_F*ky,&su,&cu);
    for(int i=0;i<8;++i){
        int y = oct*8+i;
        u16 ch,cl,sh,sl; splitbf(c,ch,cl); splitbf(s,sh,sl);
        u32* pa = (u32*)(g_opA + (size_t)m*KOP + 6*y);
        pa[0]=(u32)ch|((u32)ch<<16); pa[1]=(u32)cl|((u32)sh<<16); pa[2]=(u32)sh|((u32)sl<<16);
        u32* pr = (u32*)(g_adjBr + (size_t)y*KADJ + 6*m);
        pr[0]=(u32)ch|((u32)cl<<16); pr[1]=(u32)ch|((u32)sh<<16); pr[2]=(u32)sl|((u32)sh<<16);
        u16 nh=sh^0x8000, nl=sl^0x8000;
        u32* pi = (u32*)(g_adjBi + (size_t)y*KADJ + 6*m);
        pi[0]=(u32)nh|((u32)nl<<16); pi[1]=(u32)nh|((u32)ch<<16); pi[2]=(u32)cl|((u32)ch<<16);
        float nc = c*cu - s*su; s = s*cu + c*su; c = nc;
    }
}
__global__ void k_build_kx(const float* __restrict__ traj){
    int m = blockIdx.x*256 + threadIdx.x;
    int oct = blockIdx.y;
    float kx = traj[2*m];
    float ph = kx*(float)(oct*8-96); float r = ph-rintf(ph);
    float s,c; __sincosf(-TWO_PI_F*r,&s,&c);
    float su,cu; __sincosf(-TWO_PI_F*kx,&su,&cu);
    for(int i=0;i<8;++i){
        int x = oct*8+i;
        g_Amr[(size_t)m*NPIX+x]=c; g_Ami[(size_t)m*NPIX+x]=s;
        g_Axr[(size_t)x*MPTS+m]=c; g_Axi[(size_t)x*MPTS+m]=s;
        float nc = c*cu - s*su; s = s*cu + c*su; c = nc;
    }
}
__global__ void k_opB(const float* __restrict__ xin, int usePipe){
    int idx = blockIdx.x*256 + threadIdx.x;
    int x = idx/192, y = idx - x*192;
    float re = usePipe ? g_pimg[idx] : xin[idx];
    float im = usePipe ? g_pimg[NN+idx] : xin[NN+idx];
    u16 rh,rl,ih,il; splitbf(re,rh,rl); splitbf(im,ih,il);
    u16 nh=ih^0x8000, nl=il^0x8000;
    u32* pr = (u32*)(g_opBr + (size_t)x*KOP + 6*y);
    pr[0]=(u32)rh|((u32)rl<<16); pr[1]=(u32)rh|((u32)nh<<16); pr[2]=(u32)nl|((u32)nh<<16);
    u32* pi = (u32*)(g_opBi + (size_t)x*KOP + 6*y);
    pi[0]=(u32)ih|((u32)il<<16); pi[1]=(u32)ih|((u32)rh<<16); pi[2]=(u32)rl|((u32)rh<<16);
}
__global__ void k_Ebuild(){
    int m = blockIdx.x*256 + threadIdx.x;
    int x = blockIdx.y;
    float dr=g_dre[m], di=g_dim[m];
    float ar=g_Axr[(size_t)x*MPTS+m], ai=g_Axi[(size_t)x*MPTS+m];
    float er = ar*dr + ai*di, ei = ar*di - ai*dr;
    u16 eh,el,fh,fl; splitbf(er,eh,el); splitbf(ei,fh,fl);
    u32* p = (u32*)(g_E + (size_t)x*KADJ + 6*m);
    p[0]=(u32)eh|((u32)eh<<16); p[1]=(u32)el|((u32)fh<<16); p[2]=(u32)fh|((u32)fl<<16);
}

// ---------------- elementwise ----------------
__global__ void k_winit(){int i=blockIdx.x*256+threadIdx.x; g_w[i]=1.0f;}
__global__ void k_dfromw(){int i=blockIdx.x*256+threadIdx.x; g_dre[i]=g_w[i]; g_dim[i]=0.0f;}
__global__ void k_wupdate(){int i=blockIdx.x*256+threadIdx.x;
    float m=sqrtf(g_sre[i]*g_sre[i]+g_sim[i]*g_sim[i]); g_w[i]=g_w[i]/fmaxf(m,1e-20f);}
__global__ void k_dscale(){int i=blockIdx.x*256+threadIdx.x;
    g_dre[i]=g_w[i]*g_sre[i]; g_dim[i]=g_w[i]*g_sim[i];}
__global__ void k_scomb(){int i=blockIdx.x*256+threadIdx.x;
    g_sre[i]=g_uv[0][i]-g_uv[3][i]; g_sim[i]=g_uv[2][i]+g_uv[1][i];}
__global__ void k_reduce(float* __restrict__ out, int mode){
    int idx = blockIdx.x*256 + threadIdx.x;     // 0..73727
    int c = idx >= NN;
    int xy = idx - (c?NN:0);
    float s = 0.f;
#pragma unroll 8
    for(int z=0;z<72;++z) s += g_part[((size_t)(c*72+z))*NN + xy];
    if(mode) out[idx]=s; else g_pimg[idx]=s;
}

// ---------------- op GEMM: T[m,x] + fused A-dot (cross-warp smem reduce) -----
__global__ void __launch_bounds__(384) k_opg(){
    extern __shared__ char dsm[];
    float acc[96];
#pragma unroll
    for(int i=0;i<96;++i) acc[i]=0.f;
    int var = blockIdx.x, blk = blockIdx.y;      // var fastest -> L2 reuse of opA
    const u16* gA = g_opA + (size_t)blk*192*KOP;
    const u16* gB = var ? g_opBi : g_opBr;
    gemm192(gA, KOP, gB, KOP, 24, dsm, acc);

    int lane = threadIdx.x&31, w = threadIdx.x>>5;
    int wm = w & 3, wn = w >> 2;
    int g = lane>>2, j3 = lane&3;
    float u1[3][2], u2[3][2];
#pragma unroll
    for(int mg=0;mg<3;++mg){ u1[mg][0]=u1[mg][1]=0.f; u2[mg][0]=u2[mg][1]=0.f; }
#pragma unroll
    for(int mg=0;mg<3;++mg){
        int m0 = blk*192 + wm*48 + mg*16 + g;
#pragma unroll
        for(int tp=0;tp<8;++tp){
            int x = wn*64 + tp*8 + 2*j3;
            const float* c = acc + (mg*8+tp)*4;
            float ar0=__ldg(&g_Amr[(size_t)m0*NPIX+x]),  ar1=__ldg(&g_Amr[(size_t)m0*NPIX+x+1]);
            float ai0=__ldg(&g_Ami[(size_t)m0*NPIX+x]),  ai1=__ldg(&g_Ami[(size_t)m0*NPIX+x+1]);
            u1[mg][0] += ar0*c[0] + ar1*c[1];
            u2[mg][0] += ai0*c[0] + ai1*c[1];
            float br0=__ldg(&g_Amr[(size_t)(m0+8)*NPIX+x]), br1=__ldg(&g_Amr[(size_t)(m0+8)*NPIX+x+1]);
            float bi0=__ldg(&g_Ami[(size_t)(m0+8)*NPIX+x]), bi1=__ldg(&g_Ami[(size_t)(m0+8)*NPIX+x+1]);
            u1[mg][1] += br0*c[2] + br1*c[3];
            u2[mg][1] += bi0*c[2] + bi1*c[3];
        }
    }
#pragma unroll
    for(int o=1;o<4;o<<=1){
#pragma unroll
        for(int mg=0;mg<3;++mg){
            u1[mg][0]+=__shfl_xor_sync(0xffffffffu,u1[mg][0],o);
            u1[mg][1]+=__shfl_xor_sync(0xffffffffu,u1[mg][1],o);
            u2[mg][0]+=__shfl_xor_sync(0xffffffffu,u2[mg][0],o);
            u2[mg][1]+=__shfl_xor_sync(0xffffffffu,u2[mg][1],o);
        }
    }
    __syncthreads();                              // done with GEMM tiles
    float* sr = (float*)dsm;                      // [wn][wm][mg][row16][2]
    if(j3==0){
#pragma unroll
        for(int mg=0;mg<3;++mg){
#pragma unroll
            for(int h=0;h<2;++h){
                int row = h*8 + g;
                int off = (((wn*4 + wm)*3 + mg)*16 + row)*2;
                sr[off]   = u1[mg][h];
                sr[off+1] = u2[mg][h];
            }
        }
    }
    __syncthreads();
    int t = threadIdx.x;
    int row192 = t >> 1, sel = t & 1;
    int twm = row192/48, rem = row192 - twm*48;
    int tmg = rem >> 4, trow = rem & 15;
    float s = 0.f;
#pragma unroll
    for(int qn=0;qn<3;++qn)
        s += sr[(((qn*4 + twm)*3 + tmg)*16 + trow)*2 + sel];
    int m = blk*192 + row192;
    float* dst = sel ? (var ? g_uv[3] : g_uv[1]) : (var ? g_uv[2] : g_uv[0]);
    dst[m] = s;
}

// ---------------- adj GEMM: split-K partials ---------------------------------
__global__ void __launch_bounds__(384) k_adjg(){
    extern __shared__ char dsm[];
    float acc[96];
#pragma unroll
    for(int i=0;i<96;++i) acc[i]=0.f;
    int var = blockIdx.x, z = blockIdx.y;        // var fastest -> L2 reuse of E
    const u16* gA = g_E + (size_t)z*3072;
    const u16* gB = (var ? g_adjBi : g_adjBr) + (size_t)z*3072;
    gemm192(gA, KADJ, gB, KADJ, 64, dsm, acc);

    int lane = threadIdx.x&31, w = threadIdx.x>>5;
    int wm = w & 3, wn = w >> 2;
    int g = lane>>2, j3 = lane&3;
    float* pp = g_part + ((size_t)var*72 + z)*NN;
#pragma unroll
    for(int mg=0;mg<3;++mg){
        int x0 = wm*48 + mg*16 + g;
#pragma unroll
        for(int tp=0;tp<8;++tp){
            int y = wn*64 + tp*8 + 2*j3;
            const float* c = acc + (mg*8+tp)*4;
            *(float2*)&pp[(size_t)x0*192+y]     = make_float2(c[0],c[1]);
            *(float2*)&pp[(size_t)(x0+8)*192+y] = make_float2(c[2],c[3]);
        }
    }
}

// ---------------- driver ----------------
extern "C" void kernel_launch(void* const* d_in, const int* in_sizes, int n_in,
                              void* d_out, int out_size) {
    const float* xin  = (const float*)d_in[0];
    const float* traj = (const float*)d_in[1];
    float* out = (float*)d_out;
    const int SMEM = 43008;      // < 48KB: no attribute opt-in required

    dim3 gb(144,24);
    k_build_ky<<<gb,256>>>(traj);
    k_build_kx<<<gb,256>>>(traj);
    k_winit<<<144,256>>>();

    for(int it=0; it<3; ++it){
        k_dfromw<<<144,256>>>();
        k_Ebuild<<<dim3(144,192),256>>>();
        k_adjg<<<dim3(2,72),384,SMEM>>>();
        k_reduce<<<288,256>>>(out,0);
        k_opB<<<144,256>>>(xin,1);
        k_opg<<<dim3(2,192),384,SMEM>>>();
        k_scomb<<<144,256>>>();
        k_wupdate<<<144,256>>>();
    }
    k_opB<<<144,256>>>(xin,0);
    k_opg<<<dim3(2,192),384,SMEM>>>();
    k_scomb<<<144,256>>>();
    k_dscale<<<144,256>>>();
    k_Ebuild<<<dim3(144,192),256>>>();
    k_adjg<<<dim3(2,72),384,SMEM>>>();
    k_reduce<<<288,256>>>(out,1);
}

// round 13
// speedup vs baseline: 2.2965x; 1.3437x over previous
#include <cuda_runtime.h>
#include <cuda_fp16.h>
#include <math.h>
#include <stdint.h>

#define NPIX 192
#define MPTS 36864
#define NN   36864
#define KOP  768           // 192*4 slots
#define KADJ 147456        // 36864*4 slots
#define ZS   64            // adj split-K CTAs per variant
#define TWO_PI_F 6.28318530717958647693f
#define ESCALE 4096.0f     // keep fp16 E-operands out of subnormal range
#define EUNSC  (1.0f/4096.0f)

typedef unsigned short u16;
typedef unsigned int   u32;

// ---------------- device globals ----------------
static __device__ __align__(16) u16 g_opA [(size_t)MPTS*KOP];      // 57MB {c,c,s,s}
static __device__ __align__(16) u16 g_opBr[(size_t)NPIX*KOP];      // {irh,irl,-iih,-iil}
static __device__ __align__(16) u16 g_opBi[(size_t)NPIX*KOP];      // {iih,iil,irh,irl}
static __device__ __align__(16) u16 g_adjBr[(size_t)NPIX*KADJ];    // 57MB {c,c,s,s}
static __device__ __align__(16) u16 g_adjBi[(size_t)NPIX*KADJ];    // 57MB {-s,-s,c,c}
static __device__ __align__(16) u16 g_E[(size_t)NPIX*KADJ];        // 57MB {erh,erl,eih,eil}
static __device__ float g_Amr[(size_t)MPTS*NPIX], g_Ami[(size_t)MPTS*NPIX];
static __device__ float g_Axr[(size_t)NPIX*MPTS], g_Axi[(size_t)NPIX*MPTS];
static __device__ float g_part[(size_t)2*ZS*NN];                   // 18.9MB
static __device__ float g_uv[4][MPTS];
static __device__ float g_w[MPTS], g_dre[MPTS], g_dim[MPTS];
static __device__ float g_pimg[2*NN];

// ---------------- helpers ----------------
__device__ __forceinline__ u32 s2u(const void* p){u32 a;asm("{ .reg .u64 t; cvta.to.shared.u64 t, %1; cvt.u32.u64 %0, t; }":"=r"(a):"l"(p));return a;}
__device__ __forceinline__ u16 h16(float v){ __half h=__float2half_rn(v); return __half_as_ushort(h); }
__device__ __forceinline__ void splith(float v,u16&h,u16&l){
    __half a=__float2half_rn(v);
    __half b=__float2half_rn(v-__half2float(a));
    h=__half_as_ushort(a); l=__half_as_ushort(b);
}
__device__ __forceinline__ void hmma(float* c,u32 a0,u32 a1,u32 a2,u32 a3,u32 b0,u32 b1){
    asm volatile("mma.sync.aligned.m16n8k16.row.col.f32.f16.f16.f32 {%0,%1,%2,%3},{%4,%5,%6,%7},{%8,%9},{%0,%1,%2,%3};"
        : "+f"(c[0]),"+f"(c[1]),"+f"(c[2]),"+f"(c[3])
        : "r"(a0),"r"(a1),"r"(a2),"r"(a3),"r"(b0),"r"(b1));
}
#define LDMX4(r0,r1,r2,r3,addr) \
    asm volatile("ldmatrix.sync.aligned.m8n8.x4.shared.b16 {%0,%1,%2,%3},[%4];" \
        : "=r"(r0),"=r"(r1),"=r"(r2),"=r"(r3) : "r"(addr))

// ---------------- GEMM core: M=192, N=192, K-chunk = 48 slots ----------------
__device__ __forceinline__ void compute192(const char* sm,float* acc){
    int lane = threadIdx.x & 31, w = threadIdx.x >> 5;
    int wm = w & 3, wn = w >> 2;
    int q = lane & 7, quad = lane >> 3;
    u32 smu = s2u(sm);
    u32 aAddr0 = smu + (u32)((wm*48 + (quad&1)*8 + q)*112 + ((quad>>1)*8)*2);
    u32 bAddr0 = smu + 21504u + (u32)((wn*64 + ((quad>>1)&1)*8 + q)*112 + ((quad&1)*8)*2);
#pragma unroll
    for(int s=0;s<3;++s){
        u32 a[3][4];
#pragma unroll
        for(int mg=0;mg<3;++mg)
            LDMX4(a[mg][0],a[mg][1],a[mg][2],a[mg][3], aAddr0 + (u32)(mg*16*112 + s*32));
#pragma unroll
        for(int ng=0;ng<4;++ng){
            u32 b0,b1,b2,b3;
            LDMX4(b0,b1,b2,b3, bAddr0 + (u32)(ng*16*112 + s*32));
#pragma unroll
            for(int mg=0;mg<3;++mg){
                hmma(acc + (mg*8 + ng*2    )*4, a[mg][0],a[mg][1],a[mg][2],a[mg][3], b0,b1);
                hmma(acc + (mg*8 + ng*2 + 1)*4, a[mg][0],a[mg][1],a[mg][2],a[mg][3], b2,b3);
            }
        }
    }
}
__device__ __forceinline__ void gemm192(const u16* gA,size_t sA,const u16* gB,size_t sB,
                                        int nch,char* sm,float* acc){
    int r = threadIdx.x >> 1, half = threadIdx.x & 1;
    uint4* dstA = (uint4*)(sm + r*112) + half*3;
    uint4* dstB = (uint4*)(sm + 21504 + r*112) + half*3;
    {
        const uint4* srcA = (const uint4*)(gA + (size_t)r*sA) + half*3;
        const uint4* srcB = (const uint4*)(gB + (size_t)r*sB) + half*3;
#pragma unroll
        for(int q=0;q<3;++q){ dstA[q]=srcA[q]; dstB[q]=srcB[q]; }
    }
    __syncthreads();
    for(int c=0;c<nch;++c){
        uint4 ra[3], rb[3];
        if(c+1<nch){
            const uint4* srcA = (const uint4*)(gA + (size_t)(c+1)*48 + (size_t)r*sA) + half*3;
            const uint4* srcB = (const uint4*)(gB + (size_t)(c+1)*48 + (size_t)r*sB) + half*3;
#pragma unroll
            for(int q=0;q<3;++q){ ra[q]=srcA[q]; rb[q]=srcB[q]; }
        }
        compute192(sm,acc);
        if(c+1<nch){
            __syncthreads();
#pragma unroll
            for(int q=0;q<3;++q){ dstA[q]=ra[q]; dstB[q]=rb[q]; }
            __syncthreads();
        }
    }
}

// ---------------- builds ----------------
__global__ void k_build_ky(const float* __restrict__ traj){
    int m = blockIdx.x*256 + threadIdx.x;
    int oct = blockIdx.y;
    float ky = traj[2*m+1];
    float ph = ky*(float)(oct*8-96); float r = ph-rintf(ph);
    float s,c; __sincosf(-TWO_PI_F*r,&s,&c);
    float su,cu; __sincosf(-TWO_PI_F*ky,&su,&cu);
    for(int i=0;i<8;++i){
        int y = oct*8+i;
        u16 ch=h16(c), sh=h16(s);
        u32 cc=(u32)ch|((u32)ch<<16), ss=(u32)sh|((u32)sh<<16);
        u32* pa = (u32*)(g_opA + (size_t)m*KOP + 4*y);
        pa[0]=cc; pa[1]=ss;
        u32* pr = (u32*)(g_adjBr + (size_t)y*KADJ + 4*m);
        pr[0]=cc; pr[1]=ss;
        u32 ns = ss ^ 0x80008000u;
        u32* pi = (u32*)(g_adjBi + (size_t)y*KADJ + 4*m);
        pi[0]=ns; pi[1]=cc;
        float nc = c*cu - s*su; s = s*cu + c*su; c = nc;
    }
}
__global__ void k_build_kx(const float* __restrict__ traj){
    int m = blockIdx.x*256 + threadIdx.x;
    int oct = blockIdx.y;
    float kx = traj[2*m];
    float ph = kx*(float)(oct*8-96); float r = ph-rintf(ph);
    float s,c; __sincosf(-TWO_PI_F*r,&s,&c);
    float su,cu; __sincosf(-TWO_PI_F*kx,&su,&cu);
    for(int i=0;i<8;++i){
        int x = oct*8+i;
        g_Amr[(size_t)m*NPIX+x]=c; g_Ami[(size_t)m*NPIX+x]=s;
        g_Axr[(size_t)x*MPTS+m]=c; g_Axi[(size_t)x*MPTS+m]=s;
        float nc = c*cu - s*su; s = s*cu + c*su; c = nc;
    }
}
__global__ void k_opB(const float* __restrict__ xin, int usePipe){
    int idx = blockIdx.x*256 + threadIdx.x;
    float re = usePipe ? g_pimg[idx] : xin[idx];
    float im = usePipe ? g_pimg[NN+idx] : xin[NN+idx];
    int x = idx/192, y = idx - x*192;
    u16 rh,rl,ih,il; splith(re,rh,rl); splith(im,ih,il);
    u32* pr = (u32*)(g_opBr + (size_t)x*KOP + 4*y);
    pr[0]=(u32)rh|((u32)rl<<16);
    pr[1]=((u32)(ih^0x8000))|((u32)(il^0x8000)<<16);
    u32* pi = (u32*)(g_opBi + (size_t)x*KOP + 4*y);
    pi[0]=(u32)ih|((u32)il<<16);
    pi[1]=(u32)rh|((u32)rl<<16);
}
// E = ESCALE * conj(Ax)*d ; pipe mode: d=(w,0). Scaling keeps fp16 splits
// in normal range (w ~ 1e-3..1e-5 would otherwise be subnormal); the adj
// epilogue multiplies partials by EUNSC (exact power of 2).
__global__ void k_Ebuild(int pipe){
    int m = blockIdx.x*256 + threadIdx.x;
    int x = blockIdx.y;
    float ar=g_Axr[(size_t)x*MPTS+m], ai=g_Axi[(size_t)x*MPTS+m];
    float er, ei;
    if(pipe){ float wv=g_w[m]*ESCALE; er = ar*wv; ei = -ai*wv; }
    else { float dr=g_dre[m]*ESCALE, di=g_dim[m]*ESCALE; er = ar*dr + ai*di; ei = ar*di - ai*dr; }
    u16 eh,el,fh,fl; splith(er,eh,el); splith(ei,fh,fl);
    u32* p = (u32*)(g_E + (size_t)x*KADJ + 4*m);
    p[0]=(u32)eh|((u32)el<<16); p[1]=(u32)fh|((u32)fl<<16);
}

// ---------------- elementwise ----------------
__global__ void k_winit(){int i=blockIdx.x*256+threadIdx.x; g_w[i]=1.0f;}
__global__ void k_scombw(){int i=blockIdx.x*256+threadIdx.x;
    float sre=g_uv[0][i]-g_uv[3][i], sim=g_uv[2][i]+g_uv[1][i];
    float m=sqrtf(sre*sre+sim*sim); g_w[i]=g_w[i]/fmaxf(m,1e-20f);}
__global__ void k_scombd(){int i=blockIdx.x*256+threadIdx.x;
    float sre=g_uv[0][i]-g_uv[3][i], sim=g_uv[2][i]+g_uv[1][i];
    g_dre[i]=g_w[i]*sre; g_dim[i]=g_w[i]*sim;}
__global__ void k_reduce(float* __restrict__ out, int mode){
    int idx = blockIdx.x*256 + threadIdx.x;     // 0..73727
    int c = idx >= NN;
    int xy = idx - (c?NN:0);
    float s = 0.f;
#pragma unroll 8
    for(int z=0;z<ZS;++z) s += g_part[((size_t)(c*ZS+z))*NN + xy];
    if(mode) out[idx]=s; else g_pimg[idx]=s;
}

// ---------------- op GEMM: T[m,x] + fused A-dot (cross-warp smem reduce) -----
__global__ void __launch_bounds__(384) k_opg(){
    extern __shared__ char dsm[];
    float acc[96];
#pragma unroll
    for(int i=0;i<96;++i) acc[i]=0.f;
    int var = blockIdx.x, blk = blockIdx.y;
    const u16* gA = g_opA + (size_t)blk*192*KOP;
    const u16* gB = var ? g_opBi : g_opBr;
    gemm192(gA, KOP, gB, KOP, 16, dsm, acc);

    int lane = threadIdx.x&31, w = threadIdx.x>>5;
    int wm = w & 3, wn = w >> 2;
    int g = lane>>2, j3 = lane&3;
    float u1[3][2], u2[3][2];
#pragma unroll
    for(int mg=0;mg<3;++mg){ u1[mg][0]=u1[mg][1]=0.f; u2[mg][0]=u2[mg][1]=0.f; }
#pragma unroll
    for(int mg=0;mg<3;++mg){
        int m0 = blk*192 + wm*48 + mg*16 + g;
#pragma unroll
        for(int tp=0;tp<8;++tp){
            int x = wn*64 + tp*8 + 2*j3;
            const float* c = acc + (mg*8+tp)*4;
            float ar0=__ldg(&g_Amr[(size_t)m0*NPIX+x]),  ar1=__ldg(&g_Amr[(size_t)m0*NPIX+x+1]);
            float ai0=__ldg(&g_Ami[(size_t)m0*NPIX+x]),  ai1=__ldg(&g_Ami[(size_t)m0*NPIX+x+1]);
            u1[mg][0] += ar0*c[0] + ar1*c[1];
            u2[mg][0] += ai0*c[0] + ai1*c[1];
            float br0=__ldg(&g_Amr[(size_t)(m0+8)*NPIX+x]), br1=__ldg(&g_Amr[(size_t)(m0+8)*NPIX+x+1]);
            float bi0=__ldg(&g_Ami[(size_t)(m0+8)*NPIX+x]), bi1=__ldg(&g_Ami[(size_t)(m0+8)*NPIX+x+1]);
            u1[mg][1] += br0*c[2] + br1*c[3];
            u2[mg][1] += bi0*c[2] + bi1*c[3];
        }
    }
#pragma unroll
    for(int o=1;o<4;o<<=1){
#pragma unroll
        for(int mg=0;mg<3;++mg){
            u1[mg][0]+=__shfl_xor_sync(0xffffffffu,u1[mg][0],o);
            u1[mg][1]+=__shfl_xor_sync(0xffffffffu,u1[mg][1],o);
            u2[mg][0]+=__shfl_xor_sync(0xffffffffu,u2[mg][0],o);
            u2[mg][1]+=__shfl_xor_sync(0xffffffffu,u2[mg][1],o);
        }
    }
    __syncthreads();
    float* sr = (float*)dsm;                      // [wn][wm][mg][row16][2]
    if(j3==0){
#pragma unroll
        for(int mg=0;mg<3;++mg){
#pragma unroll
            for(int h=0;h<2;++h){
                int row = h*8 + g;
                int off = (((wn*4 + wm)*3 + mg)*16 + row)*2;
                sr[off]   = u1[mg][h];
                sr[off+1] = u2[mg][h];
            }
        }
    }
    __syncthreads();
    int t = threadIdx.x;
    int row192 = t >> 1, sel = t & 1;
    int twm = row192/48, rem = row192 - twm*48;
    int tmg = rem >> 4, trow = rem & 15;
    float s = 0.f;
#pragma unroll
    for(int qn=0;qn<3;++qn)
        s += sr[(((qn*4 + twm)*3 + tmg)*16 + trow)*2 + sel];
    int m = blk*192 + row192;
    float* dst = sel ? (var ? g_uv[3] : g_uv[1]) : (var ? g_uv[2] : g_uv[0]);
    dst[m] = s;
}

// ---------------- adj GEMM: split-K partials (unscaled by EUNSC) -------------
__global__ void __launch_bounds__(384) k_adjg(){
    extern __shared__ char dsm[];
    float acc[96];
#pragma unroll
    for(int i=0;i<96;++i) acc[i]=0.f;
    int var = blockIdx.x, z = blockIdx.y;        // var fastest -> L2 reuse of E
    const u16* gA = g_E + (size_t)z*2304;
    const u16* gB = (var ? g_adjBi : g_adjBr) + (size_t)z*2304;
    gemm192(gA, KADJ, gB, KADJ, 48, dsm, acc);

    int lane = threadIdx.x&31, w = threadIdx.x>>5;
    int wm = w & 3, wn = w >> 2;
    int g = lane>>2, j3 = lane&3;
    float* pp = g_part + ((size_t)var*ZS + z)*NN;
#pragma unroll
    for(int mg=0;mg<3;++mg){
        int x0 = wm*48 + mg*16 + g;
#pragma unroll
        for(int tp=0;tp<8;++tp){
            int y = wn*64 + tp*8 + 2*j3;
            const float* c = acc + (mg*8+tp)*4;
            *(float2*)&pp[(size_t)x0*192+y]     = make_float2(c[0]*EUNSC,c[1]*EUNSC);
            *(float2*)&pp[(size_t)(x0+8)*192+y] = make_float2(c[2]*EUNSC,c[3]*EUNSC);
        }
    }
}

// ---------------- driver ----------------
extern "C" void kernel_launch(void* const* d_in, const int* in_sizes, int n_in,
                              void* d_out, int out_size) {
    const float* xin  = (const float*)d_in[0];
    const float* traj = (const float*)d_in[1];
    float* out = (float*)d_out;
    const int SMEM = 43008;      // < 48KB: no attribute opt-in required

    dim3 gb(144,24);
    k_build_ky<<<gb,256>>>(traj);
    k_build_kx<<<gb,256>>>(traj);
    k_winit<<<144,256>>>();

    for(int it=0; it<3; ++it){
        k_Ebuild<<<dim3(144,192),256>>>(1);
        k_adjg<<<dim3(2,ZS),384,SMEM>>>();
        k_reduce<<<288,256>>>(out,0);
        k_opB<<<144,256>>>(xin,1);
        k_opg<<<dim3(2,192),384,SMEM>>>();
        k_scombw<<<144,256>>>();
    }
    k_opB<<<144,256>>>(xin,0);
    k_opg<<<dim3(2,192),384,SMEM>>>();
    k_scombd<<<144,256>>>();
    k_Ebuild<<<dim3(144,192),256>>>(0);
    k_adjg<<<dim3(2,ZS),384,SMEM>>>();
    k_reduce<<<288,256>>>(out,1);
}

// round 14
// speedup vs baseline: 2.7277x; 1.1878x over previous
#include <cuda_runtime.h>
#include <cuda_fp16.h>
#include <math.h>
#include <stdint.h>

#define NPIX 192
#define MPTS 36864
#define NN   36864
#define KOP  768           // 192*4 slots
#define KADJ 147456        // 36864*4 slots
#define ZS   64            // adj split-K CTAs per variant
#define TWO_PI_F 6.28318530717958647693f
#define ESCALE 4096.0f
#define EUNSC  (1.0f/4096.0f)

typedef unsigned short u16;
typedef unsigned int   u32;
typedef unsigned long long u64;

// ---------------- device globals ----------------
static __device__ __align__(16) u16 g_opA [(size_t)MPTS*KOP];      // 57MB {c,c,s,s}
static __device__ __align__(16) u16 g_opBr[(size_t)NPIX*KOP];      // {irh,irl,-iih,-iil}
static __device__ __align__(16) u16 g_opBi[(size_t)NPIX*KOP];      // {iih,iil,irh,irl}
static __device__ __align__(16) u16 g_adjBr[(size_t)NPIX*KADJ];    // 57MB {c,c,s,s} (var1 derives by E-permute)
static __device__ __align__(16) u16 g_E[(size_t)NPIX*KADJ];        // 57MB {erh,erl,eih,eil}
static __device__ u32 g_Am[(size_t)MPTS*NPIX];                     // 28MB packed (c,s) fp16 [m][x]
static __device__ u32 g_Ax[(size_t)NPIX*MPTS];                     // 28MB packed (c,s) fp16 [x][m]
static __device__ float g_part[(size_t)2*ZS*NN];                   // 18.9MB
static __device__ float g_uv[4][MPTS];
static __device__ float g_w[MPTS], g_dre[MPTS], g_dim[MPTS];

// ---------------- helpers ----------------
__device__ __forceinline__ u32 s2u(const void* p){u32 a;asm("{ .reg .u64 t; cvta.to.shared.u64 t, %1; cvt.u32.u64 %0, t; }":"=r"(a):"l"(p));return a;}
__device__ __forceinline__ u16 h16(float v){ __half h=__float2half_rn(v); return __half_as_ushort(h); }
__device__ __forceinline__ void splith(float v,u16&h,u16&l){
    __half a=__float2half_rn(v);
    __half b=__float2half_rn(v-__half2float(a));
    h=__half_as_ushort(a); l=__half_as_ushort(b);
}
__device__ __forceinline__ float2 up16(u32 v){
    __half2 h = *reinterpret_cast<__half2*>(&v);
    return __half22float2(h);
}
__device__ __forceinline__ void hmma(float* c,u32 a0,u32 a1,u32 a2,u32 a3,u32 b0,u32 b1){
    asm volatile("mma.sync.aligned.m16n8k16.row.col.f32.f16.f16.f32 {%0,%1,%2,%3},{%4,%5,%6,%7},{%8,%9},{%0,%1,%2,%3};"
        : "+f"(c[0]),"+f"(c[1]),"+f"(c[2]),"+f"(c[3])
        : "r"(a0),"r"(a1),"r"(a2),"r"(a3),"r"(b0),"r"(b1));
}
#define LDMX4(r0,r1,r2,r3,addr) \
    asm volatile("ldmatrix.sync.aligned.m8n8.x4.shared.b16 {%0,%1,%2,%3},[%4];" \
        : "=r"(r0),"=r"(r1),"=r"(r2),"=r"(r3) : "r"(addr))

// A-permute for adj var1: per m, E={er,ei} -> E'={ei, -er}
__device__ __forceinline__ uint4 permE(uint4 v){
    uint4 r; r.x=v.y; r.y=v.x^0x80008000u; r.z=v.w; r.w=v.z^0x80008000u; return r;
}

// ---------------- GEMM core: M=192, N=192, K-chunk = 48 slots ----------------
__device__ __forceinline__ void compute192(const char* sm,float* acc){
    int lane = threadIdx.x & 31, w = threadIdx.x >> 5;
    int wm = w & 3, wn = w >> 2;
    int q = lane & 7, quad = lane >> 3;
    u32 smu = s2u(sm);
    u32 aAddr0 = smu + (u32)((wm*48 + (quad&1)*8 + q)*112 + ((quad>>1)*8)*2);
    u32 bAddr0 = smu + 21504u + (u32)((wn*64 + ((quad>>1)&1)*8 + q)*112 + ((quad&1)*8)*2);
#pragma unroll
    for(int s=0;s<3;++s){
        u32 a[3][4];
#pragma unroll
        for(int mg=0;mg<3;++mg)
            LDMX4(a[mg][0],a[mg][1],a[mg][2],a[mg][3], aAddr0 + (u32)(mg*16*112 + s*32));
#pragma unroll
        for(int ng=0;ng<4;++ng){
            u32 b0,b1,b2,b3;
            LDMX4(b0,b1,b2,b3, bAddr0 + (u32)(ng*16*112 + s*32));
#pragma unroll
            for(int mg=0;mg<3;++mg){
                hmma(acc + (mg*8 + ng*2    )*4, a[mg][0],a[mg][1],a[mg][2],a[mg][3], b0,b1);
                hmma(acc + (mg*8 + ng*2 + 1)*4, a[mg][0],a[mg][1],a[mg][2],a[mg][3], b2,b3);
            }
        }
    }
}
__device__ __forceinline__ void gemm192(const u16* gA,size_t sA,const u16* gB,size_t sB,
                                        int nch,char* sm,float* acc,int permA){
    int r = threadIdx.x >> 1, half = threadIdx.x & 1;
    uint4* dstA = (uint4*)(sm + r*112) + half*3;
    uint4* dstB = (uint4*)(sm + 21504 + r*112) + half*3;
    {
        const uint4* srcA = (const uint4*)(gA + (size_t)r*sA) + half*3;
        const uint4* srcB = (const uint4*)(gB + (size_t)r*sB) + half*3;
#pragma unroll
        for(int q=0;q<3;++q){
            uint4 va = srcA[q];
            dstA[q] = permA ? permE(va) : va;
            dstB[q] = srcB[q];
        }
    }
    __syncthreads();
    for(int c=0;c<nch;++c){
        uint4 ra[3], rb[3];
        if(c+1<nch){
            const uint4* srcA = (const uint4*)(gA + (size_t)(c+1)*48 + (size_t)r*sA) + half*3;
            const uint4* srcB = (const uint4*)(gB + (size_t)(c+1)*48 + (size_t)r*sB) + half*3;
#pragma unroll
            for(int q=0;q<3;++q){ ra[q]=srcA[q]; rb[q]=srcB[q]; }
        }
        compute192(sm,acc);
        if(c+1<nch){
            __syncthreads();
#pragma unroll
            for(int q=0;q<3;++q){
                dstA[q] = permA ? permE(ra[q]) : ra[q];
                dstB[q] = rb[q];
            }
            __syncthreads();
        }
    }
}

// ---------------- builds ----------------
__global__ void k_build_ky(const float* __restrict__ traj){
    int m = blockIdx.x*256 + threadIdx.x;
    int oct = blockIdx.y;
    float ky = traj[2*m+1];
    float ph = ky*(float)(oct*8-96); float r = ph-rintf(ph);
    float s,c; __sincosf(-TWO_PI_F*r,&s,&c);
    float su,cu; __sincosf(-TWO_PI_F*ky,&su,&cu);
    for(int i=0;i<8;++i){
        int y = oct*8+i;
        u16 ch=h16(c), sh=h16(s);
        u32 cc=(u32)ch|((u32)ch<<16), ss=(u32)sh|((u32)sh<<16);
        u32* pa = (u32*)(g_opA + (size_t)m*KOP + 4*y);
        pa[0]=cc; pa[1]=ss;
        u32* pr = (u32*)(g_adjBr + (size_t)y*KADJ + 4*m);
        pr[0]=cc; pr[1]=ss;
        float nc = c*cu - s*su; s = s*cu + c*su; c = nc;
    }
}
__global__ void k_build_kx(const float* __restrict__ traj){
    int m = blockIdx.x*256 + threadIdx.x;
    int oct = blockIdx.y;
    float kx = traj[2*m];
    float ph = kx*(float)(oct*8-96); float r = ph-rintf(ph);
    float s,c; __sincosf(-TWO_PI_F*r,&s,&c);
    float su,cu; __sincosf(-TWO_PI_F*kx,&su,&cu);
    for(int i=0;i<8;++i){
        int x = oct*8+i;
        u32 pk = (u32)h16(c) | ((u32)h16(s)<<16);
        g_Am[(size_t)m*NPIX+x]=pk; g_Ax[(size_t)x*MPTS+m]=pk;
        float nc = c*cu - s*su; s = s*cu + c*su; c = nc;
    }
}
// real-image op B build (final op only)
__global__ void k_opB(const float* __restrict__ xin){
    int idx = blockIdx.x*256 + threadIdx.x;
    float re = xin[idx], im = xin[NN+idx];
    int x = idx/192, y = idx - x*192;
    u16 rh,rl,ih,il; splith(re,rh,rl); splith(im,ih,il);
    u32* pr = (u32*)(g_opBr + (size_t)x*KOP + 4*y);
    pr[0]=(u32)rh|((u32)rl<<16);
    pr[1]=((u32)(ih^0x8000))|((u32)(il^0x8000)<<16);
    u32* pi = (u32*)(g_opBi + (size_t)x*KOP + 4*y);
    pi[0]=(u32)ih|((u32)il<<16);
    pi[1]=(u32)rh|((u32)rl<<16);
}
// E = ESCALE * conj(Ax)*d ; pipe: d=(w,0)
__global__ void k_Ebuild(int pipe){
    int m = blockIdx.x*256 + threadIdx.x;
    int x = blockIdx.y;
    float2 cs = up16(g_Ax[(size_t)x*MPTS+m]);
    float ar=cs.x, ai=cs.y;
    float er, ei;
    if(pipe){ float wv=g_w[m]*ESCALE; er = ar*wv; ei = -ai*wv; }
    else { float dr=g_dre[m]*ESCALE, di=g_dim[m]*ESCALE; er = ar*dr + ai*di; ei = ar*di - ai*dr; }
    u16 eh,el,fh,fl; splith(er,eh,el); splith(ei,fh,fl);
    u32* p = (u32*)(g_E + (size_t)x*KADJ + 4*m);
    p[0]=(u32)eh|((u32)el<<16); p[1]=(u32)fh|((u32)fl<<16);
}

// ---------------- elementwise ----------------
__global__ void k_winit(){int i=blockIdx.x*256+threadIdx.x; g_w[i]=1.0f;}
__global__ void k_scombw(){int i=blockIdx.x*256+threadIdx.x;
    float sre=g_uv[0][i]-g_uv[3][i], sim=g_uv[2][i]+g_uv[1][i];
    float m=sqrtf(sre*sre+sim*sim); g_w[i]=g_w[i]/fmaxf(m,1e-20f);}
__global__ void k_scombd(){int i=blockIdx.x*256+threadIdx.x;
    float sre=g_uv[0][i]-g_uv[3][i], sim=g_uv[2][i]+g_uv[1][i];
    g_dre[i]=g_w[i]*sre; g_dim[i]=g_w[i]*sim;}
// pipe-image reduce fused with op-B packing (skips the pimg round trip)
__global__ void k_reduceB(){
    int idx = blockIdx.x*256 + threadIdx.x;      // 0..NN-1, = x*192+y
    float re=0.f, im=0.f;
#pragma unroll 8
    for(int z=0;z<ZS;++z){
        re += g_part[(size_t)z*NN + idx];
        im += g_part[((size_t)(ZS+z))*NN + idx];
    }
    int x = idx/192, y = idx - x*192;
    u16 rh,rl,ih,il; splith(re,rh,rl); splith(im,ih,il);
    u32* pr = (u32*)(g_opBr + (size_t)x*KOP + 4*y);
    pr[0]=(u32)rh|((u32)rl<<16);
    pr[1]=((u32)(ih^0x8000))|((u32)(il^0x8000)<<16);
    u32* pi = (u32*)(g_opBi + (size_t)x*KOP + 4*y);
    pi[0]=(u32)ih|((u32)il<<16);
    pi[1]=(u32)rh|((u32)rl<<16);
}
__global__ void k_reduceOut(float* __restrict__ out){
    int idx = blockIdx.x*256 + threadIdx.x;      // 0..73727
    int c = idx >= NN;
    int xy = idx - (c?NN:0);
    float s = 0.f;
#pragma unroll 8
    for(int z=0;z<ZS;++z) s += g_part[((size_t)(c*ZS+z))*NN + xy];
    out[idx]=s;
}

// ---------------- op GEMM: T[m,x] + fused A-dot (cross-warp smem reduce) -----
__global__ void __launch_bounds__(384) k_opg(){
    extern __shared__ char dsm[];
    float acc[96];
#pragma unroll
    for(int i=0;i<96;++i) acc[i]=0.f;
    int var = blockIdx.x, blk = blockIdx.y;
    const u16* gA = g_opA + (size_t)blk*192*KOP;
    const u16* gB = var ? g_opBi : g_opBr;
    gemm192(gA, KOP, gB, KOP, 16, dsm, acc, 0);

    int lane = threadIdx.x&31, w = threadIdx.x>>5;
    int wm = w & 3, wn = w >> 2;
    int g = lane>>2, j3 = lane&3;
    float u1[3][2], u2[3][2];
#pragma unroll
    for(int mg=0;mg<3;++mg){ u1[mg][0]=u1[mg][1]=0.f; u2[mg][0]=u2[mg][1]=0.f; }
#pragma unroll
    for(int mg=0;mg<3;++mg){
        int m0 = blk*192 + wm*48 + mg*16 + g;
#pragma unroll
        for(int tp=0;tp<8;++tp){
            int x = wn*64 + tp*8 + 2*j3;
            const float* c = acc + (mg*8+tp)*4;
            u64 w0 = __ldg((const u64*)(g_Am + (size_t)m0*NPIX + x));
            float2 cs0 = up16((u32)w0), cs1 = up16((u32)(w0>>32));
            u1[mg][0] += cs0.x*c[0] + cs1.x*c[1];
            u2[mg][0] += cs0.y*c[0] + cs1.y*c[1];
            u64 w1 = __ldg((const u64*)(g_Am + (size_t)(m0+8)*NPIX + x));
            float2 ds0 = up16((u32)w1), ds1 = up16((u32)(w1>>32));
            u1[mg][1] += ds0.x*c[2] + ds1.x*c[3];
            u2[mg][1] += ds0.y*c[2] + ds1.y*c[3];
        }
    }
#pragma unroll
    for(int o=1;o<4;o<<=1){
#pragma unroll
        for(int mg=0;mg<3;++mg){
            u1[mg][0]+=__shfl_xor_sync(0xffffffffu,u1[mg][0],o);
            u1[mg][1]+=__shfl_xor_sync(0xffffffffu,u1[mg][1],o);
            u2[mg][0]+=__shfl_xor_sync(0xffffffffu,u2[mg][0],o);
            u2[mg][1]+=__shfl_xor_sync(0xffffffffu,u2[mg][1],o);
        }
    }
    __syncthreads();
    float* sr = (float*)dsm;                      // [wn][wm][mg][row16][2]
    if(j3==0){
#pragma unroll
        for(int mg=0;mg<3;++mg){
#pragma unroll
            for(int h=0;h<2;++h){
                int row = h*8 + g;
                int off = (((wn*4 + wm)*3 + mg)*16 + row)*2;
                sr[off]   = u1[mg][h];
                sr[off+1] = u2[mg][h];
            }
        }
    }
    __syncthreads();
    int t = threadIdx.x;
    int row192 = t >> 1, sel = t & 1;
    int twm = row192/48, rem = row192 - twm*48;
    int tmg = rem >> 4, trow = rem & 15;
    float s = 0.f;
#pragma unroll
    for(int qn=0;qn<3;++qn)
        s += sr[(((qn*4 + twm)*3 + tmg)*16 + trow)*2 + sel];
    int m = blk*192 + row192;
    float* dst = sel ? (var ? g_uv[3] : g_uv[1]) : (var ? g_uv[2] : g_uv[0]);
    dst[m] = s;
}

// ---------------- adj GEMM: split-K partials ---------------------------------
__global__ void __launch_bounds__(384) k_adjg(){
    extern __shared__ char dsm[];
    float acc[96];
#pragma unroll
    for(int i=0;i<96;++i) acc[i]=0.f;
    int var = blockIdx.x, z = blockIdx.y;        // var fastest -> L2 reuse of E AND adjBr
    const u16* gA = g_E + (size_t)z*2304;
    const u16* gB = g_adjBr + (size_t)z*2304;    // var1 uses same B, permuted E
    gemm192(gA, KADJ, gB, KADJ, 48, dsm, acc, var);

    int lane = threadIdx.x&31, w = threadIdx.x>>5;
    int wm = w & 3, wn = w >> 2;
    int g = lane>>2, j3 = lane&3;
    float* pp = g_part + ((size_t)var*ZS + z)*NN;
#pragma unroll
    for(int mg=0;mg<3;++mg){
        int x0 = wm*48 + mg*16 + g;
#pragma unroll
        for(int tp=0;tp<8;++tp){
            int y = wn*64 + tp*8 + 2*j3;
            const float* c = acc + (mg*8+tp)*4;
            *(float2*)&pp[(size_t)x0*192+y]     = make_float2(c[0]*EUNSC,c[1]*EUNSC);
            *(float2*)&pp[(size_t)(x0+8)*192+y] = make_float2(c[2]*EUNSC,c[3]*EUNSC);
        }
    }
}

// ---------------- driver ----------------
extern "C" void kernel_launch(void* const* d_in, const int* in_sizes, int n_in,
                              void* d_out, int out_size) {
    const float* xin  = (const float*)d_in[0];
    const float* traj = (const float*)d_in[1];
    float* out = (float*)d_out;
    const int SMEM = 43008;      // < 48KB: no attribute opt-in required

    dim3 gb(144,24);
    k_build_ky<<<gb,256>>>(traj);
    k_build_kx<<<gb,256>>>(traj);
    k_winit<<<144,256>>>();

    for(int it=0; it<3; ++it){
        k_Ebuild<<<dim3(144,192),256>>>(1);
        k_adjg<<<dim3(2,ZS),384,SMEM>>>();
        k_reduceB<<<144,256>>>();
        k_opg<<<dim3(2,192),384,SMEM>>>();
        k_scombw<<<144,256>>>();
    }
    k_opB<<<144,256>>>(xin);
    k_opg<<<dim3(2,192),384,SMEM>>>();
    k_scombd<<<144,256>>>();
    k_Ebuild<<<dim3(144,192),256>>>(0);
    k_adjg<<<dim3(2,ZS),384,SMEM>>>();
    k_reduceOut<<<288,256>>>(out);
}

// round 15
// speedup vs baseline: 2.8024x; 1.0274x over previous
#include <cuda_runtime.h>
#include <cuda_fp16.h>
#include <math.h>
#include <stdint.h>

#define NPIX 192
#define MPTS 36864
#define NN   36864
#define KOP  768           // 192*4 slots
#define KADJ 147456        // 36864*4 slots
#define ZS   64
#define TWO_PI_F 6.28318530717958647693f
#define ESCALE 4096.0f
#define EUNSC  (1.0f/4096.0f)

typedef unsigned short u16;
typedef unsigned int   u32;
typedef unsigned long long u64;

// ---------------- device globals ----------------
static __device__ __align__(16) u32 g_opAp[(size_t)MPTS*NPIX];     // 28MB packed {c,s} [m][y]
static __device__ __align__(16) u32 g_adjBp[(size_t)NPIX*MPTS];    // 28MB packed {c,s} [y][m]
static __device__ __align__(16) u16 g_opBr[(size_t)NPIX*KOP];
static __device__ __align__(16) u16 g_opBi[(size_t)NPIX*KOP];
static __device__ __align__(16) u16 g_E[(size_t)NPIX*KADJ];        // 57MB {erh,erl,eih,eil}
static __device__ u32 g_Am[(size_t)MPTS*NPIX];                     // 28MB packed (c,s) [m][x]
static __device__ u32 g_Ax[(size_t)NPIX*MPTS];                     // 28MB packed (c,s) [x][m]
static __device__ float g_part[(size_t)2*ZS*NN];
static __device__ float g_uv[4][MPTS];
static __device__ float g_w[MPTS], g_dre[MPTS], g_dim[MPTS];

// ---------------- helpers ----------------
__device__ __forceinline__ u32 s2u(const void* p){u32 a;asm("{ .reg .u64 t; cvta.to.shared.u64 t, %1; cvt.u32.u64 %0, t; }":"=r"(a):"l"(p));return a;}
__device__ __forceinline__ u16 h16(float v){ __half h=__float2half_rn(v); return __half_as_ushort(h); }
__device__ __forceinline__ void splith(float v,u16&h,u16&l){
    __half a=__float2half_rn(v);
    __half b=__float2half_rn(v-__half2float(a));
    h=__half_as_ushort(a); l=__half_as_ushort(b);
}
__device__ __forceinline__ float2 up16(u32 v){
    __half2 h = *reinterpret_cast<__half2*>(&v);
    return __half22float2(h);
}
__device__ __forceinline__ u32 prmt(u32 v,u32 sel){u32 r;asm("prmt.b32 %0,%1,%1,%2;":"=r"(r):"r"(v),"r"(sel));return r;}
__device__ __forceinline__ void hmma(float* c,u32 a0,u32 a1,u32 a2,u32 a3,u32 b0,u32 b1){
    asm volatile("mma.sync.aligned.m16n8k16.row.col.f32.f16.f16.f32 {%0,%1,%2,%3},{%4,%5,%6,%7},{%8,%9},{%0,%1,%2,%3};"
        : "+f"(c[0]),"+f"(c[1]),"+f"(c[2]),"+f"(c[3])
        : "r"(a0),"r"(a1),"r"(a2),"r"(a3),"r"(b0),"r"(b1));
}
#define LDMX4(r0,r1,r2,r3,addr) \
    asm volatile("ldmatrix.sync.aligned.m8n8.x4.shared.b16 {%0,%1,%2,%3},[%4];" \
        : "=r"(r0),"=r"(r1),"=r"(r2),"=r"(r3) : "r"(addr))
__device__ __forceinline__ uint4 permE(uint4 v){
    uint4 r; r.x=v.y; r.y=v.x^0x80008000u; r.z=v.w; r.w=v.z^0x80008000u; return r;
}

// ---------------- staging: packed (48B->96B via PRMT) or raw 96B -------------
__device__ __forceinline__ void stage_ld(const void* src,int packed,size_t stride,int c,int r,uint4* v){
    if(packed){
        const uint4* s = (const uint4*)((const u32*)src + (size_t)r*stride + c*12);
        v[0]=s[0]; v[1]=s[1]; v[2]=s[2];
    } else {
        const uint4* s = (const uint4*)((const u16*)src + (size_t)r*stride + c*48);
#pragma unroll
        for(int q=0;q<6;++q) v[q]=s[q];
    }
}
__device__ __forceinline__ void stage_st(char* dst,int packed,int perm,const uint4* v){
    uint4* d=(uint4*)dst;
    if(packed){
#pragma unroll
        for(int q=0;q<3;++q){
            uint4 pv=v[q], o1, o2;
            o1.x=prmt(pv.x,0x1010u); o1.y=prmt(pv.x,0x3232u);
            o1.z=prmt(pv.y,0x1010u); o1.w=prmt(pv.y,0x3232u);
            o2.x=prmt(pv.z,0x1010u); o2.y=prmt(pv.z,0x3232u);
            o2.z=prmt(pv.w,0x1010u); o2.w=prmt(pv.w,0x3232u);
            d[2*q]=o1; d[2*q+1]=o2;
        }
    } else {
#pragma unroll
        for(int q=0;q<6;++q) d[q] = perm ? permE(v[q]) : v[q];
    }
}

// ---------------- GEMM core: M=192, N=192, K-chunk = 48 slots ----------------
__device__ __forceinline__ void compute192(const char* sm,float* acc){
    int lane = threadIdx.x & 31, w = threadIdx.x >> 5;
    int wm = w & 3, wn = w >> 2;
    int q = lane & 7, quad = lane >> 3;
    u32 smu = s2u(sm);
    u32 aAddr0 = smu + (u32)((wm*48 + (quad&1)*8 + q)*112 + ((quad>>1)*8)*2);
    u32 bAddr0 = smu + 21504u + (u32)((wn*64 + ((quad>>1)&1)*8 + q)*112 + ((quad&1)*8)*2);
#pragma unroll
    for(int s=0;s<3;++s){
        u32 a[3][4];
#pragma unroll
        for(int mg=0;mg<3;++mg)
            LDMX4(a[mg][0],a[mg][1],a[mg][2],a[mg][3], aAddr0 + (u32)(mg*16*112 + s*32));
#pragma unroll
        for(int ng=0;ng<4;++ng){
            u32 b0,b1,b2,b3;
            LDMX4(b0,b1,b2,b3, bAddr0 + (u32)(ng*16*112 + s*32));
#pragma unroll
            for(int mg=0;mg<3;++mg){
                hmma(acc + (mg*8 + ng*2    )*4, a[mg][0],a[mg][1],a[mg][2],a[mg][3], b0,b1);
                hmma(acc + (mg*8 + ng*2 + 1)*4, a[mg][0],a[mg][1],a[mg][2],a[mg][3], b2,b3);
            }
        }
    }
}
__device__ __forceinline__ void gemm192(const void* gA,size_t sA,int pA,int permA,
                                        const void* gB,size_t sB,int pB,
                                        int nch,char* sm,float* acc){
    int t = threadIdx.x;
    int role = t >= 192;
    int r = role ? t-192 : t;
    const void* src = role ? gB : gA;
    int packed = role ? pB : pA;
    size_t stride = role ? sB : sA;
    int perm = role ? 0 : permA;
    char* dst = sm + (role?21504:0) + r*112;
    uint4 v[6];
    stage_ld(src,packed,stride,0,r,v);
    stage_st(dst,packed,perm,v);
    __syncthreads();
    for(int c=0;c<nch;++c){
        if(c+1<nch) stage_ld(src,packed,stride,c+1,r,v);
        compute192(sm,acc);
        if(c+1<nch){
            __syncthreads();
            stage_st(dst,packed,perm,v);
            __syncthreads();
        }
    }
}

// ---------------- builds ----------------
__global__ void k_build_ky(const float* __restrict__ traj){
    int m = blockIdx.x*256 + threadIdx.x;
    int oct = blockIdx.y;
    float ky = traj[2*m+1];
    float ph = ky*(float)(oct*8-96); float r = ph-rintf(ph);
    float s,c; __sincosf(-TWO_PI_F*r,&s,&c);
    float su,cu; __sincosf(-TWO_PI_F*ky,&su,&cu);
    for(int i=0;i<8;++i){
        int y = oct*8+i;
        u32 pk = (u32)h16(c) | ((u32)h16(s)<<16);
        g_opAp[(size_t)m*NPIX + y] = pk;
        g_adjBp[(size_t)y*MPTS + m] = pk;
        float nc = c*cu - s*su; s = s*cu + c*su; c = nc;
    }
}
__global__ void k_build_kx(const float* __restrict__ traj){
    int m = blockIdx.x*256 + threadIdx.x;
    int oct = blockIdx.y;
    float kx = traj[2*m];
    float ph = kx*(float)(oct*8-96); float r = ph-rintf(ph);
    float s,c; __sincosf(-TWO_PI_F*r,&s,&c);
    float su,cu; __sincosf(-TWO_PI_F*kx,&su,&cu);
    for(int i=0;i<8;++i){
        int x = oct*8+i;
        u32 pk = (u32)h16(c) | ((u32)h16(s)<<16);
        g_Am[(size_t)m*NPIX+x]=pk; g_Ax[(size_t)x*MPTS+m]=pk;
        float nc = c*cu - s*su; s = s*cu + c*su; c = nc;
    }
}
__global__ void k_opB(const float* __restrict__ xin){
    int idx = blockIdx.x*256 + threadIdx.x;
    float re = xin[idx], im = xin[NN+idx];
    int x = idx/192, y = idx - x*192;
    u16 rh,rl,ih,il; splith(re,rh,rl); splith(im,ih,il);
    u32* pr = (u32*)(g_opBr + (size_t)x*KOP + 4*y);
    pr[0]=(u32)rh|((u32)rl<<16);
    pr[1]=((u32)(ih^0x8000))|((u32)(il^0x8000)<<16);
    u32* pi = (u32*)(g_opBi + (size_t)x*KOP + 4*y);
    pi[0]=(u32)ih|((u32)il<<16);
    pi[1]=(u32)rh|((u32)rl<<16);
}
// E = ESCALE * conj(Ax)*d ; pipe: d=(w,0). 2 m per thread, uint4 store.
__global__ void k_Ebuild(int pipe){
    int m0 = (blockIdx.x*256 + threadIdx.x)*2;
    int x = blockIdx.y;
    u64 w2 = *(const u64*)(g_Ax + (size_t)x*MPTS + m0);
    uint4 o;
#pragma unroll
    for(int j=0;j<2;++j){
        float2 cs = up16(j ? (u32)(w2>>32) : (u32)w2);
        int m = m0 + j;
        float er, ei;
        if(pipe){ float wv=g_w[m]*ESCALE; er = cs.x*wv; ei = -cs.y*wv; }
        else { float dr=g_dre[m]*ESCALE, di=g_dim[m]*ESCALE;
               er = cs.x*dr + cs.y*di; ei = cs.x*di - cs.y*dr; }
        u16 eh,el,fh,fl; splith(er,eh,el); splith(ei,fh,fl);
        if(j==0){ o.x=(u32)eh|((u32)el<<16); o.y=(u32)fh|((u32)fl<<16); }
        else     { o.z=(u32)eh|((u32)el<<16); o.w=(u32)fh|((u32)fl<<16); }
    }
    *(uint4*)(g_E + (size_t)x*KADJ + 4*m0) = o;
}

// ---------------- elementwise ----------------
__global__ void k_winit(){int i=blockIdx.x*256+threadIdx.x; g_w[i]=1.0f;}
__global__ void k_scombw(){int i=blockIdx.x*256+threadIdx.x;
    float sre=g_uv[0][i]-g_uv[3][i], sim=g_uv[2][i]+g_uv[1][i];
    float m=sqrtf(sre*sre+sim*sim); g_w[i]=g_w[i]/fmaxf(m,1e-20f);}
__global__ void k_scombd(){int i=blockIdx.x*256+threadIdx.x;
    float sre=g_uv[0][i]-g_uv[3][i], sim=g_uv[2][i]+g_uv[1][i];
    g_dre[i]=g_w[i]*sre; g_dim[i]=g_w[i]*sim;}
__global__ void k_reduceB(){
    int idx = blockIdx.x*256 + threadIdx.x;
    float re=0.f, im=0.f;
#pragma unroll 8
    for(int z=0;z<ZS;++z){
        re += g_part[(size_t)z*NN + idx];
        im += g_part[((size_t)(ZS+z))*NN + idx];
    }
    int x = idx/192, y = idx - x*192;
    u16 rh,rl,ih,il; splith(re,rh,rl); splith(im,ih,il);
    u32* pr = (u32*)(g_opBr + (size_t)x*KOP + 4*y);
    pr[0]=(u32)rh|((u32)rl<<16);
    pr[1]=((u32)(ih^0x8000))|((u32)(il^0x8000)<<16);
    u32* pi = (u32*)(g_opBi + (size_t)x*KOP + 4*y);
    pi[0]=(u32)ih|((u32)il<<16);
    pi[1]=(u32)rh|((u32)rl<<16);
}
__global__ void k_reduceOut(float* __restrict__ out){
    int idx = blockIdx.x*256 + threadIdx.x;
    int c = idx >= NN;
    int xy = idx - (c?NN:0);
    float s = 0.f;
#pragma unroll 8
    for(int z=0;z<ZS;++z) s += g_part[((size_t)(c*ZS+z))*NN + xy];
    out[idx]=s;
}

// ---------------- op GEMM ------------------------------------------------------
__global__ void __launch_bounds__(384) k_opg(){
    extern __shared__ char dsm[];
    float acc[96];
#pragma unroll
    for(int i=0;i<96;++i) acc[i]=0.f;
    int var = blockIdx.x, blk = blockIdx.y;
    const u32* gA = g_opAp + (size_t)blk*192*NPIX;
    const u16* gB = var ? g_opBi : g_opBr;
    gemm192(gA, NPIX, 1, 0, gB, KOP, 0, 16, dsm, acc);

    int lane = threadIdx.x&31, w = threadIdx.x>>5;
    int wm = w & 3, wn = w >> 2;
    int g = lane>>2, j3 = lane&3;
    float u1[3][2], u2[3][2];
#pragma unroll
    for(int mg=0;mg<3;++mg){ u1[mg][0]=u1[mg][1]=0.f; u2[mg][0]=u2[mg][1]=0.f; }
#pragma unroll
    for(int mg=0;mg<3;++mg){
        int m0 = blk*192 + wm*48 + mg*16 + g;
#pragma unroll
        for(int tp=0;tp<8;++tp){
            int x = wn*64 + tp*8 + 2*j3;
            const float* c = acc + (mg*8+tp)*4;
            u64 w0 = __ldg((const u64*)(g_Am + (size_t)m0*NPIX + x));
            float2 cs0 = up16((u32)w0), cs1 = up16((u32)(w0>>32));
            u1[mg][0] += cs0.x*c[0] + cs1.x*c[1];
            u2[mg][0] += cs0.y*c[0] + cs1.y*c[1];
            u64 w1 = __ldg((const u64*)(g_Am + (size_t)(m0+8)*NPIX + x));
            float2 ds0 = up16((u32)w1), ds1 = up16((u32)(w1>>32));
            u1[mg][1] += ds0.x*c[2] + ds1.x*c[3];
            u2[mg][1] += ds0.y*c[2] + ds1.y*c[3];
        }
    }
#pragma unroll
    for(int o=1;o<4;o<<=1){
#pragma unroll
        for(int mg=0;mg<3;++mg){
            u1[mg][0]+=__shfl_xor_sync(0xffffffffu,u1[mg][0],o);
            u1[mg][1]+=__shfl_xor_sync(0xffffffffu,u1[mg][1],o);
            u2[mg][0]+=__shfl_xor_sync(0xffffffffu,u2[mg][0],o);
            u2[mg][1]+=__shfl_xor_sync(0xffffffffu,u2[mg][1],o);
        }
    }
    __syncthreads();
    float* sr = (float*)dsm;
    if(j3==0){
#pragma unroll
        for(int mg=0;mg<3;++mg){
#pragma unroll
            for(int h=0;h<2;++h){
                int row = h*8 + g;
                int off = (((wn*4 + wm)*3 + mg)*16 + row)*2;
                sr[off]   = u1[mg][h];
                sr[off+1] = u2[mg][h];
            }
        }
    }
    __syncthreads();
    int t = threadIdx.x;
    int row192 = t >> 1, sel = t & 1;
    int twm = row192/48, rem = row192 - twm*48;
    int tmg = rem >> 4, trow = rem & 15;
    float s = 0.f;
#pragma unroll
    for(int qn=0;qn<3;++qn)
        s += sr[(((qn*4 + twm)*3 + tmg)*16 + trow)*2 + sel];
    int m = blk*192 + row192;
    float* dst = sel ? (var ? g_uv[3] : g_uv[1]) : (var ? g_uv[2] : g_uv[0]);
    dst[m] = s;
}

// ---------------- adj GEMM -----------------------------------------------------
__global__ void __launch_bounds__(384) k_adjg(){
    extern __shared__ char dsm[];
    float acc[96];
#pragma unroll
    for(int i=0;i<96;++i) acc[i]=0.f;
    int var = blockIdx.x, z = blockIdx.y;
    const u16* gA = g_E + (size_t)z*2304;
    const u32* gB = g_adjBp + (size_t)z*576;
    gemm192(gA, KADJ, 0, var, gB, MPTS, 1, 48, dsm, acc);

    int lane = threadIdx.x&31, w = threadIdx.x>>5;
    int wm = w & 3, wn = w >> 2;
    int g = lane>>2, j3 = lane&3;
    float* pp = g_part + ((size_t)var*ZS + z)*NN;
#pragma unroll
    for(int mg=0;mg<3;++mg){
        int x0 = wm*48 + mg*16 + g;
#pragma unroll
        for(int tp=0;tp<8;++tp){
            int y = wn*64 + tp*8 + 2*j3;
            const float* c = acc + (mg*8+tp)*4;
            *(float2*)&pp[(size_t)x0*192+y]     = make_float2(c[0]*EUNSC,c[1]*EUNSC);
            *(float2*)&pp[(size_t)(x0+8)*192+y] = make_float2(c[2]*EUNSC,c[3]*EUNSC);
        }
    }
}

// ---------------- driver ----------------
extern "C" void kernel_launch(void* const* d_in, const int* in_sizes, int n_in,
                              void* d_out, int out_size) {
    const float* xin  = (const float*)d_in[0];
    const float* traj = (const float*)d_in[1];
    float* out = (float*)d_out;
    const int SMEM = 43008;

    dim3 gb(144,24);
    k_build_ky<<<gb,256>>>(traj);
    k_build_kx<<<gb,256>>>(traj);
    k_winit<<<144,256>>>();

    for(int it=0; it<3; ++it){
        k_Ebuild<<<dim3(72,192),256>>>(1);
        k_adjg<<<dim3(2,ZS),384,SMEM>>>();
        k_reduceB<<<144,256>>>();
        k_opg<<<dim3(2,192),384,SMEM>>>();
        k_scombw<<<144,256>>>();
    }
    k_opB<<<144,256>>>(xin);
    k_opg<<<dim3(2,192),384,SMEM>>>();
    k_scombd<<<144,256>>>();
    k_Ebuild<<<dim3(72,192),256>>>(0);
    k_adjg<<<dim3(2,ZS),384,SMEM>>>();
    k_reduceOut<<<288,256>>>(out);
}